// round 1
// baseline (speedup 1.0000x reference)
#include <cuda_runtime.h>

#define B_  64
#define J_  512
#define P_  768
#define NC_ 16
#define DC_ 64
#define WN_ 1024   // NC_*DC_

// ---------------- scratch (device globals; no allocation allowed) ----------------
__device__ float g_xbar[4][B_ * P_];          // colsum partials  [jsplit][b*P+p]
__device__ float g_o[B_ * NC_ * DC_];         // routed outputs   [b][i][k]
__device__ float g_v[B_ * P_ * NC_];          // W_i @ o          [b][p][i]  (i contiguous)
__device__ float g_c[B_ * J_ * NC_];          // softmax coeffs   [b][j][i]  (i contiguous)
__device__ float g_yp[4][B_ * NC_ * P_];      // y partials       [jsplit][b][i][p]

// ---------------- packed f32x2 helpers ----------------
__device__ __forceinline__ unsigned long long ffma2(unsigned long long a,
                                                    unsigned long long b,
                                                    unsigned long long c) {
    unsigned long long d;
    asm("fma.rn.f32x2 %0, %1, %2, %3;" : "=l"(d) : "l"(a), "l"(b), "l"(c));
    return d;
}
__device__ __forceinline__ unsigned long long pack2(float v) {
    unsigned long long d;
    unsigned int u = __float_as_uint(v);
    asm("mov.b64 %0, {%1, %1};" : "=l"(d) : "r"(u));
    return d;
}
__device__ __forceinline__ float2 unpack2(unsigned long long u) {
    float2 f;
    f.x = __uint_as_float((unsigned int)u);
    f.y = __uint_as_float((unsigned int)(u >> 32));
    return f;
}

// ---------------- K1: xbar partials  (reads x once, coalesced) ----------------
__global__ void k_colsum(const float* __restrict__ x) {
    int p  = blockIdx.x * 256 + threadIdx.x;   // 3 blocks cover 768
    int js = blockIdx.y;                       // 4 j-splits of 128
    int b  = blockIdx.z;
    const float* xp = x + ((size_t)b * J_ + (size_t)js * 128) * P_ + p;
    float a0 = 0.f, a1 = 0.f, a2 = 0.f, a3 = 0.f;
    #pragma unroll 8
    for (int j = 0; j < 128; j += 4) {
        a0 += xp[(size_t)(j + 0) * P_];
        a1 += xp[(size_t)(j + 1) * P_];
        a2 += xp[(size_t)(j + 2) * P_];
        a3 += xp[(size_t)(j + 3) * P_];
    }
    g_xbar[js][b * P_ + p] = (a0 + a1) + (a2 + a3);
}

// ---------------- K2/K6: s = src @ W_i, then squash (L2-normalize over k) ------
// MODE 0: src = sum of xbar partials (i-independent), scaled by 1/16
// MODE 1: src = sum of y partials [b][i][p]
// grid (i=16, bgroup=8), block 256. warp w -> b=b0+w, lane l -> k in {l, l+32}.
template <int MODE>
__global__ void __launch_bounds__(256) k_sq(const float* __restrict__ W,
                                            float* __restrict__ out) {
    int i  = blockIdx.x;
    int b0 = blockIdx.y * 8;
    __shared__ float ys[8][P_];
    for (int idx = threadIdx.x; idx < 8 * P_; idx += 256) {
        int bb = idx / P_, pp = idx - bb * P_;
        float s;
        if (MODE == 0) {
            int off = (b0 + bb) * P_ + pp;
            s = g_xbar[0][off] + g_xbar[1][off] + g_xbar[2][off] + g_xbar[3][off];
        } else {
            size_t off = ((size_t)(b0 + bb) * NC_ + i) * P_ + pp;
            s = g_yp[0][off] + g_yp[1][off] + g_yp[2][off] + g_yp[3][off];
        }
        ys[bb][pp] = s;
    }
    __syncthreads();
    int w = threadIdx.x >> 5, l = threadIdx.x & 31;
    const float* Wp = W + i * DC_;
    float a0 = 0.f, a1 = 0.f, a2 = 0.f, a3 = 0.f;
    #pragma unroll 4
    for (int p = 0; p < P_; p += 2) {
        float y0 = ys[w][p], y1 = ys[w][p + 1];
        a0 += y0 * Wp[(size_t)p * WN_ + l];
        a1 += y0 * Wp[(size_t)p * WN_ + l + 32];
        a2 += y1 * Wp[(size_t)(p + 1) * WN_ + l];
        a3 += y1 * Wp[(size_t)(p + 1) * WN_ + l + 32];
    }
    a0 += a2; a1 += a3;
    if (MODE == 0) { a0 *= 0.0625f; a1 *= 0.0625f; }   // uniform c = 1/16
    float sq = a0 * a0 + a1 * a1;
    #pragma unroll
    for (int s = 16; s > 0; s >>= 1) sq += __shfl_xor_sync(0xffffffffu, sq, s);
    float r = rsqrtf(sq + 1e-7f);
    float* dst = out ? out : g_o;
    size_t ob = ((size_t)(b0 + w) * NC_ + i) * DC_ + l;
    dst[ob]      = a0 * r;
    dst[ob + 32] = a1 * r;
}

// ---------------- K3: v[b][p][i] = sum_k W[p][i*64+k] * o[b][i][k] -------------
// grid (i=16, bgroup=8), block 256. Each thread owns 3 p values.
__global__ void __launch_bounds__(256) k_vproj(const float* __restrict__ W) {
    int i  = blockIdx.x;
    int b0 = blockIdx.y * 8;
    __shared__ float os[8][DC_];
    for (int idx = threadIdx.x; idx < 8 * DC_; idx += 256)
        os[idx >> 6][idx & 63] = g_o[((size_t)(b0 + (idx >> 6)) * NC_ + i) * DC_ + (idx & 63)];
    __syncthreads();
    for (int p = threadIdx.x; p < P_; p += 256) {
        const float4* Wp = (const float4*)(W + (size_t)p * WN_ + i * DC_);
        float acc[8] = {0.f, 0.f, 0.f, 0.f, 0.f, 0.f, 0.f, 0.f};
        #pragma unroll
        for (int c = 0; c < 16; c++) {
            float4 wq = Wp[c];
            #pragma unroll
            for (int bb = 0; bb < 8; bb++)
                acc[bb] += wq.x * os[bb][4 * c]     + wq.y * os[bb][4 * c + 1]
                         + wq.z * os[bb][4 * c + 2] + wq.w * os[bb][4 * c + 3];
        }
        #pragma unroll
        for (int bb = 0; bb < 8; bb++)
            g_v[((size_t)(b0 + bb) * P_ + p) * NC_ + i] = acc[bb];
    }
}

// ---------------- K4: blog[b,i,j] = x[b,j,:].v[b,:,i] , fused softmax over i ---
// grid (jblk=4, b=64), block 128; thread owns one full j-row (all 16 i, all p).
// v tile lives in smem (48KB); all v LDS are warp-broadcast (conflict-free).
__global__ void __launch_bounds__(128) k_route(const float* __restrict__ x) {
    int b  = blockIdx.y;
    int jg = blockIdx.x * 128 + threadIdx.x;
    __shared__ float4 vs[P_][4];                       // [p][16 floats] = 48KB
    const float4* vsrc = (const float4*)(g_v + (size_t)b * P_ * NC_);
    for (int idx = threadIdx.x; idx < P_ * 4; idx += 128)
        vs[idx >> 2][idx & 3] = vsrc[idx];
    __syncthreads();

    const float4* xp = (const float4*)(x + ((size_t)b * J_ + jg) * P_);
    unsigned long long acc[8];
    #pragma unroll
    for (int q = 0; q < 8; q++) acc[q] = 0ull;

    #pragma unroll 4
    for (int pg = 0; pg < P_ / 4; pg++) {
        float4 xq = xp[pg];
        float xv[4] = {xq.x, xq.y, xq.z, xq.w};
        #pragma unroll
        for (int c = 0; c < 4; c++) {
            unsigned long long xx = pack2(xv[c]);
            const ulonglong2* vrow = (const ulonglong2*)(&vs[4 * pg + c][0]);
            ulonglong2 va = vrow[0], vb = vrow[1], vc2 = vrow[2], vd = vrow[3];
            acc[0] = ffma2(xx, va.x,  acc[0]);
            acc[1] = ffma2(xx, va.y,  acc[1]);
            acc[2] = ffma2(xx, vb.x,  acc[2]);
            acc[3] = ffma2(xx, vb.y,  acc[3]);
            acc[4] = ffma2(xx, vc2.x, acc[4]);
            acc[5] = ffma2(xx, vc2.y, acc[5]);
            acc[6] = ffma2(xx, vd.x,  acc[6]);
            acc[7] = ffma2(xx, vd.y,  acc[7]);
        }
    }

    float bl[16];
    #pragma unroll
    for (int q = 0; q < 8; q++) {
        float2 f = unpack2(acc[q]);
        bl[2 * q] = f.x; bl[2 * q + 1] = f.y;
    }
    float m = bl[0];
    #pragma unroll
    for (int q = 1; q < 16; q++) m = fmaxf(m, bl[q]);
    float sum = 0.f;
    #pragma unroll
    for (int q = 0; q < 16; q++) { bl[q] = __expf(bl[q] - m); sum += bl[q]; }
    float inv = 1.0f / sum;
    float4* cp = (float4*)(g_c + ((size_t)b * J_ + jg) * NC_);
    #pragma unroll
    for (int q = 0; q < 4; q++)
        cp[q] = make_float4(bl[4 * q] * inv, bl[4 * q + 1] * inv,
                            bl[4 * q + 2] * inv, bl[4 * q + 3] * inv);
}

// ---------------- K5: y[b][i][p] += c[b][j][i] * x[b][j][p]  (j-split partials)
// grid (jsplit=4, b=64), block 256; thread owns p in {t, t+256, t+512}, all 16 i.
__global__ void __launch_bounds__(256) k_y(const float* __restrict__ x) {
    int b  = blockIdx.y;
    int js = blockIdx.x;
    int j0 = js * 128;
    int t  = threadIdx.x;
    __shared__ float4 cs[128][4];                      // [j][16 floats] = 8KB
    const float4* csrc = (const float4*)(g_c + ((size_t)b * J_ + j0) * NC_);
    for (int idx = t; idx < 512; idx += 256) cs[idx >> 2][idx & 3] = csrc[idx];
    __syncthreads();

    unsigned long long acc[24];
    #pragma unroll
    for (int q = 0; q < 24; q++) acc[q] = 0ull;
    const float* xb = x + ((size_t)b * J_ + j0) * P_;

    #pragma unroll 2
    for (int j = 0; j < 128; j++) {
        float x0 = xb[(size_t)j * P_ + t];
        float x1 = xb[(size_t)j * P_ + t + 256];
        float x2 = xb[(size_t)j * P_ + t + 512];
        unsigned long long xx0 = pack2(x0), xx1 = pack2(x1), xx2 = pack2(x2);
        const ulonglong2* crow = (const ulonglong2*)(&cs[j][0]);
        ulonglong2 ca = crow[0], cb = crow[1], cc = crow[2], cd = crow[3];
        unsigned long long cq[8] = {ca.x, ca.y, cb.x, cb.y, cc.x, cc.y, cd.x, cd.y};
        #pragma unroll
        for (int q = 0; q < 8; q++) {
            acc[q]      = ffma2(xx0, cq[q], acc[q]);
            acc[8 + q]  = ffma2(xx1, cq[q], acc[8 + q]);
            acc[16 + q] = ffma2(xx2, cq[q], acc[16 + q]);
        }
    }

    #pragma unroll
    for (int pp = 0; pp < 3; pp++) {
        #pragma unroll
        for (int q = 0; q < 8; q++) {
            float2 f = unpack2(acc[pp * 8 + q]);
            g_yp[js][((size_t)b * NC_ + 2 * q)     * P_ + pp * 256 + t] = f.x;
            g_yp[js][((size_t)b * NC_ + 2 * q + 1) * P_ + pp * 256 + t] = f.y;
        }
    }
}

// ---------------- launch ----------------
extern "C" void kernel_launch(void* const* d_in, const int* in_sizes, int n_in,
                              void* d_out, int out_size) {
    const float* x = (const float*)d_in[0];
    const float* W = (const float*)d_in[1];
    if (n_in >= 2 && in_sizes[0] < in_sizes[1]) {  // x is the big tensor; be robust to order
        const float* tmp = x; x = W; W = tmp;
    }
    float* out = (float*)d_out;
    (void)out_size;

    // o0 = squash(xbar @ W)
    k_colsum<<<dim3(3, 4, 64), 256>>>(x);
    k_sq<0><<<dim3(16, 8), 256>>>(W, nullptr);

    // two routing refinements; last one writes d_out
    for (int it = 0; it < 2; it++) {
        k_vproj<<<dim3(16, 8), 256>>>(W);
        k_route<<<dim3(4, 64), 128>>>(x);
        k_y<<<dim3(4, 64), 256>>>(x);
        k_sq<1><<<dim3(16, 8), 256>>>(W, (it == 1) ? out : nullptr);
    }
}

// round 2
// speedup vs baseline: 1.0134x; 1.0134x over previous
#include <cuda_runtime.h>

#define B_  64
#define J_  512
#define P_  768
#define NC_ 16
#define DC_ 64
#define WN_ 1024   // NC_*DC_

typedef unsigned long long ull;

// ---------------- scratch (device globals; no allocation allowed) ----------------
__device__ float g_xbar[4][B_ * P_];          // colsum partials  [jsplit][b*P+p]
__device__ float g_v[B_ * P_ * NC_];          // W_i @ o          [b][p][i]  (i contiguous)
__device__ float g_c[B_ * J_ * NC_];          // softmax coeffs   [b][j][i]  (i contiguous)
__device__ float g_yp[4][B_ * NC_ * P_];      // y partials       [jsplit][b][i][p]

// ---------------- packed f32x2 helpers ----------------
__device__ __forceinline__ ull ffma2(ull a, ull b, ull c) {
    ull d;
    asm("fma.rn.f32x2 %0, %1, %2, %3;" : "=l"(d) : "l"(a), "l"(b), "l"(c));
    return d;
}
__device__ __forceinline__ ull pack2(float v) {
    ull d;
    unsigned int u = __float_as_uint(v);
    asm("mov.b64 %0, {%1, %1};" : "=l"(d) : "r"(u));
    return d;
}
__device__ __forceinline__ float2 unpack2(ull u) {
    float2 f;
    f.x = __uint_as_float((unsigned int)u);
    f.y = __uint_as_float((unsigned int)(u >> 32));
    return f;
}

// ---------------- K1: xbar partials  (reads x once, coalesced) ----------------
__global__ void k_colsum(const float* __restrict__ x) {
    int p  = blockIdx.x * 256 + threadIdx.x;   // 3 blocks cover 768
    int js = blockIdx.y;                       // 4 j-splits of 128
    int b  = blockIdx.z;
    const float* xp = x + ((size_t)b * J_ + (size_t)js * 128) * P_ + p;
    float a0 = 0.f, a1 = 0.f, a2 = 0.f, a3 = 0.f;
    #pragma unroll 8
    for (int j = 0; j < 128; j += 4) {
        a0 += xp[(size_t)(j + 0) * P_];
        a1 += xp[(size_t)(j + 1) * P_];
        a2 += xp[(size_t)(j + 2) * P_];
        a3 += xp[(size_t)(j + 3) * P_];
    }
    g_xbar[js][b * P_ + p] = (a0 + a1) + (a2 + a3);
}

// ---------------- K2: s = src @ W_i, squash, optional out, optional v-projection
// MODE 0: src = sum of xbar partials (uniform c => scale 1/16)
// MODE 1: src = sum of y partials [b][i][p]
// grid (i=16, bgroup=16), block 128 (warp w -> b = b0+w).
// Lane map: qk = l&15 (k-quad, k=4*qk), pofs = l>>4 (p parity).
// Warp LDG.128 covers 2 W-rows x 64 k  (4 cache lines / instr).
template <int MODE, bool WRITE_V>
__global__ void __launch_bounds__(128) k_sq(const float* __restrict__ W,
                                            float* __restrict__ out) {
    int i  = blockIdx.x;
    int b0 = blockIdx.y * 4;
    __shared__ float ys[4][P_];
    // stage src rows (vectorized)
    for (int idx = threadIdx.x; idx < 4 * (P_ / 4); idx += 128) {
        int bb = idx / (P_ / 4), pq = idx - bb * (P_ / 4);
        float4 s;
        if (MODE == 0) {
            size_t off = (size_t)(b0 + bb) * P_;
            float4 v0 = ((const float4*)(g_xbar[0] + off))[pq];
            float4 v1 = ((const float4*)(g_xbar[1] + off))[pq];
            float4 v2 = ((const float4*)(g_xbar[2] + off))[pq];
            float4 v3 = ((const float4*)(g_xbar[3] + off))[pq];
            s.x = (v0.x + v1.x) + (v2.x + v3.x);
            s.y = (v0.y + v1.y) + (v2.y + v3.y);
            s.z = (v0.z + v1.z) + (v2.z + v3.z);
            s.w = (v0.w + v1.w) + (v2.w + v3.w);
        } else {
            size_t off = ((size_t)(b0 + bb) * NC_ + i) * P_;
            float4 v0 = ((const float4*)(g_yp[0] + off))[pq];
            float4 v1 = ((const float4*)(g_yp[1] + off))[pq];
            float4 v2 = ((const float4*)(g_yp[2] + off))[pq];
            float4 v3 = ((const float4*)(g_yp[3] + off))[pq];
            s.x = (v0.x + v1.x) + (v2.x + v3.x);
            s.y = (v0.y + v1.y) + (v2.y + v3.y);
            s.z = (v0.z + v1.z) + (v2.z + v3.z);
            s.w = (v0.w + v1.w) + (v2.w + v3.w);
        }
        ((float4*)ys[bb])[pq] = s;
    }
    __syncthreads();

    int w = threadIdx.x >> 5, l = threadIdx.x & 31;
    int b = b0 + w;
    int qk = l & 15, pofs = l >> 4;
    const float* wb = W + i * DC_ + 4 * qk;

    float4 A = make_float4(0.f, 0.f, 0.f, 0.f);
    float4 Bc = make_float4(0.f, 0.f, 0.f, 0.f);
    #pragma unroll 4
    for (int p0 = 0; p0 < P_; p0 += 4) {
        float y0 = ys[w][p0 + pofs];
        float4 w0 = *(const float4*)(wb + (size_t)(p0 + pofs) * WN_);
        A.x += w0.x * y0; A.y += w0.y * y0; A.z += w0.z * y0; A.w += w0.w * y0;
        float y1 = ys[w][p0 + 2 + pofs];
        float4 w1 = *(const float4*)(wb + (size_t)(p0 + 2 + pofs) * WN_);
        Bc.x += w1.x * y1; Bc.y += w1.y * y1; Bc.z += w1.z * y1; Bc.w += w1.w * y1;
    }
    float4 acc;
    acc.x = A.x + Bc.x; acc.y = A.y + Bc.y; acc.z = A.z + Bc.z; acc.w = A.w + Bc.w;
    // combine the two p-parity halves (lanes l and l^16 share qk)
    acc.x += __shfl_xor_sync(0xffffffffu, acc.x, 16);
    acc.y += __shfl_xor_sync(0xffffffffu, acc.y, 16);
    acc.z += __shfl_xor_sync(0xffffffffu, acc.z, 16);
    acc.w += __shfl_xor_sync(0xffffffffu, acc.w, 16);
    if (MODE == 0) {
        acc.x *= 0.0625f; acc.y *= 0.0625f; acc.z *= 0.0625f; acc.w *= 0.0625f;
    }
    float sq = acc.x * acc.x + acc.y * acc.y + acc.z * acc.z + acc.w * acc.w;
    #pragma unroll
    for (int s = 8; s > 0; s >>= 1) sq += __shfl_xor_sync(0xffffffffu, sq, s);
    float r = rsqrtf(sq + 1e-7f);
    acc.x *= r; acc.y *= r; acc.z *= r; acc.w *= r;

    if (out != nullptr && l < 16)
        *(float4*)(out + ((size_t)b * NC_ + i) * DC_ + 4 * qk) = acc;

    if (WRITE_V) {
        // v[b][p][i] = sum_k W[p][i*64+k] * o[k]; same coalesced W lane map
        #pragma unroll 4
        for (int p0 = 0; p0 < P_; p0 += 2) {
            float4 wq = *(const float4*)(wb + (size_t)(p0 + pofs) * WN_);
            float part = wq.x * acc.x + wq.y * acc.y + wq.z * acc.z + wq.w * acc.w;
            part += __shfl_xor_sync(0xffffffffu, part, 1);
            part += __shfl_xor_sync(0xffffffffu, part, 2);
            part += __shfl_xor_sync(0xffffffffu, part, 4);
            part += __shfl_xor_sync(0xffffffffu, part, 8);
            if (qk == 0)
                g_v[((size_t)b * P_ + p0 + pofs) * NC_ + i] = part;
        }
    }
}

// ---------------- K3: blog[b,i,j] = x[b,j,:].v[b,:,i], fused softmax over i ---
// grid (jblk=8, b=64), block 128. Thread-halves split the p range (384 each);
// partial logits combined through padded smem, softmax by first 64 threads.
__global__ void __launch_bounds__(128) k_route(const float* __restrict__ x) {
    int b  = blockIdx.y;
    int j0 = blockIdx.x * 64;
    __shared__ float4 vs[P_][4];                       // [p][16 floats] = 48KB
    __shared__ float pb[2][64][17];                    // padded partial logits
    const float4* vsrc = (const float4*)(g_v + (size_t)b * P_ * NC_);
    for (int idx = threadIdx.x; idx < P_ * 4; idx += 128)
        vs[idx >> 2][idx & 3] = vsrc[idx];
    __syncthreads();

    int jj = threadIdx.x & 63, half = threadIdx.x >> 6;
    int j = j0 + jj;
    const float4* xp = (const float4*)x + ((size_t)(b * J_ + j) * (P_ / 4) + half * 96);
    int pbase = half * 384;

    ull acc[8];
    #pragma unroll
    for (int q = 0; q < 8; q++) acc[q] = 0ull;

    float4 xq = xp[0];
    #pragma unroll 2
    for (int pg = 0; pg < 96; pg++) {
        float4 xn = xq;
        if (pg < 95) xn = xp[pg + 1];
        float xv[4] = {xq.x, xq.y, xq.z, xq.w};
        #pragma unroll
        for (int c = 0; c < 4; c++) {
            ull xx = pack2(xv[c]);
            const ulonglong2* vrow = (const ulonglong2*)(&vs[pbase + 4 * pg + c][0]);
            ulonglong2 va = vrow[0], vb = vrow[1], vc2 = vrow[2], vd = vrow[3];
            acc[0] = ffma2(xx, va.x,  acc[0]);
            acc[1] = ffma2(xx, va.y,  acc[1]);
            acc[2] = ffma2(xx, vb.x,  acc[2]);
            acc[3] = ffma2(xx, vb.y,  acc[3]);
            acc[4] = ffma2(xx, vc2.x, acc[4]);
            acc[5] = ffma2(xx, vc2.y, acc[5]);
            acc[6] = ffma2(xx, vd.x,  acc[6]);
            acc[7] = ffma2(xx, vd.y,  acc[7]);
        }
        xq = xn;
    }
    #pragma unroll
    for (int q = 0; q < 8; q++) {
        float2 f = unpack2(acc[q]);
        pb[half][jj][2 * q]     = f.x;
        pb[half][jj][2 * q + 1] = f.y;
    }
    __syncthreads();

    if (threadIdx.x < 64) {
        int jt = threadIdx.x;
        float bl[16];
        #pragma unroll
        for (int q = 0; q < 16; q++) bl[q] = pb[0][jt][q] + pb[1][jt][q];
        float m = bl[0];
        #pragma unroll
        for (int q = 1; q < 16; q++) m = fmaxf(m, bl[q]);
        float sum = 0.f;
        #pragma unroll
        for (int q = 0; q < 16; q++) { bl[q] = __expf(bl[q] - m); sum += bl[q]; }
        float inv = 1.0f / sum;
        float4* cp = (float4*)(g_c + ((size_t)b * J_ + j0 + jt) * NC_);
        #pragma unroll
        for (int q = 0; q < 4; q++)
            cp[q] = make_float4(bl[4 * q] * inv, bl[4 * q + 1] * inv,
                                bl[4 * q + 2] * inv, bl[4 * q + 3] * inv);
    }
}

// ---------------- K4: y[b][i][p] += c[b][j][i] * x[b][j][p]  (j-split partials)
// grid (jsplit=4, b=64), block 256; thread owns p in {t, t+256, t+512}, all 16 i.
__global__ void __launch_bounds__(256) k_y(const float* __restrict__ x) {
    int b  = blockIdx.y;
    int js = blockIdx.x;
    int j0 = js * 128;
    int t  = threadIdx.x;
    __shared__ float4 cs[128][4];                      // [j][16 floats] = 8KB
    const float4* csrc = (const float4*)(g_c + ((size_t)b * J_ + j0) * NC_);
    for (int idx = t; idx < 512; idx += 256) cs[idx >> 2][idx & 3] = csrc[idx];
    __syncthreads();

    ull acc[24];
    #pragma unroll
    for (int q = 0; q < 24; q++) acc[q] = 0ull;
    const float* xb = x + ((size_t)b * J_ + j0) * P_;

    float x0 = xb[t], x1 = xb[t + 256], x2 = xb[t + 512];
    #pragma unroll 2
    for (int j = 0; j < 128; j++) {
        float n0 = x0, n1 = x1, n2 = x2;
        if (j < 127) {
            const float* xn = xb + (size_t)(j + 1) * P_;
            n0 = xn[t]; n1 = xn[t + 256]; n2 = xn[t + 512];
        }
        ull xx0 = pack2(x0), xx1 = pack2(x1), xx2 = pack2(x2);
        const ulonglong2* crow = (const ulonglong2*)(&cs[j][0]);
        ulonglong2 ca = crow[0], cb = crow[1], cc = crow[2], cd = crow[3];
        ull cq[8] = {ca.x, ca.y, cb.x, cb.y, cc.x, cc.y, cd.x, cd.y};
        #pragma unroll
        for (int q = 0; q < 8; q++) {
            acc[q]      = ffma2(xx0, cq[q], acc[q]);
            acc[8 + q]  = ffma2(xx1, cq[q], acc[8 + q]);
            acc[16 + q] = ffma2(xx2, cq[q], acc[16 + q]);
        }
        x0 = n0; x1 = n1; x2 = n2;
    }

    #pragma unroll
    for (int pp = 0; pp < 3; pp++) {
        #pragma unroll
        for (int q = 0; q < 8; q++) {
            float2 f = unpack2(acc[pp * 8 + q]);
            g_yp[js][((size_t)b * NC_ + 2 * q)     * P_ + pp * 256 + t] = f.x;
            g_yp[js][((size_t)b * NC_ + 2 * q + 1) * P_ + pp * 256 + t] = f.y;
        }
    }
}

// ---------------- launch ----------------
extern "C" void kernel_launch(void* const* d_in, const int* in_sizes, int n_in,
                              void* d_out, int out_size) {
    const float* x = (const float*)d_in[0];
    const float* W = (const float*)d_in[1];
    if (n_in >= 2 && in_sizes[0] < in_sizes[1]) {  // x is the big tensor
        const float* tmp = x; x = W; W = tmp;
    }
    float* out = (float*)d_out;
    (void)out_size;

    dim3 gsq(16, 16);

    // o0 = squash(xbar @ W), fused v-projection
    k_colsum<<<dim3(3, 4, 64), 256>>>(x);
    k_sq<0, true><<<gsq, 128>>>(W, nullptr);

    // iteration 1
    k_route<<<dim3(8, 64), 128>>>(x);
    k_y<<<dim3(4, 64), 256>>>(x);
    k_sq<1, true><<<gsq, 128>>>(W, nullptr);

    // iteration 2 (final: write out, no v needed)
    k_route<<<dim3(8, 64), 128>>>(x);
    k_y<<<dim3(4, 64), 256>>>(x);
    k_sq<1, false><<<gsq, 128>>>(W, out);
}

// round 3
// speedup vs baseline: 1.1907x; 1.1750x over previous
#include <cuda_runtime.h>

#define B_  64
#define J_  512
#define P_  768
#define NC_ 16
#define DC_ 64
#define WN_ 1024   // NC_*DC_

typedef unsigned long long ull;

// ---------------- scratch (device globals; no allocation allowed) ----------------
__device__ float  g_xbar[4][B_ * P_];       // colsum partials [jsplit][b*P+p]
__device__ float  g_o[B_ * WN_];            // routed outputs  [b][i][k] (i*64+k)
__device__ float2 g_vT[B_][8][P_];          // v transposed    [b][ipair][p]
__device__ float  g_yp[4][B_ * NC_ * P_];   // y partials      [jsplit][b][i][p]

// ---------------- packed f32x2 helpers ----------------
__device__ __forceinline__ ull ffma2(ull a, ull b, ull c) {
    ull d;
    asm("fma.rn.f32x2 %0, %1, %2, %3;" : "=l"(d) : "l"(a), "l"(b), "l"(c));
    return d;
}
__device__ __forceinline__ ull pack2(float v) {
    ull d; unsigned int u = __float_as_uint(v);
    asm("mov.b64 %0, {%1, %1};" : "=l"(d) : "r"(u));
    return d;
}
__device__ __forceinline__ ull packf2(float a, float b) {
    ull d;
    asm("mov.b64 %0, {%1, %2};" : "=l"(d) : "f"(a), "f"(b));
    return d;
}
__device__ __forceinline__ float2 unpack2(ull u) {
    float2 f;
    f.x = __uint_as_float((unsigned int)u);
    f.y = __uint_as_float((unsigned int)(u >> 32));
    return f;
}

// ---------------- K1: xbar partials (reads x once, coalesced) ----------------
__global__ void k_colsum(const float* __restrict__ x) {
    int p  = blockIdx.x * 256 + threadIdx.x;
    int js = blockIdx.y;
    int b  = blockIdx.z;
    const float* xp = x + ((size_t)b * J_ + (size_t)js * 128) * P_ + p;
    float a0 = 0.f, a1 = 0.f, a2 = 0.f, a3 = 0.f;
    #pragma unroll 8
    for (int j = 0; j < 128; j += 4) {
        a0 += xp[(size_t)(j + 0) * P_];
        a1 += xp[(size_t)(j + 1) * P_];
        a2 += xp[(size_t)(j + 2) * P_];
        a3 += xp[(size_t)(j + 3) * P_];
    }
    g_xbar[js][b * P_ + p] = (a0 + a1) + (a2 + a3);
}

// ---------------- K2: s = src @ W_i, squash -> g_o (and out when final) -------
// MODE 0: src = sum of xbar partials (uniform c => scale 1/16)
// MODE 1: src = sum of y partials [b][i][p]
// grid (i=16, bgroup=16), block 128 (warp w -> b = b0+w).
template <int MODE>
__global__ void __launch_bounds__(128) k_sq(const float* __restrict__ W,
                                            float* __restrict__ out) {
    int i  = blockIdx.x;
    int b0 = blockIdx.y * 4;
    __shared__ float ys[4][P_];
    for (int idx = threadIdx.x; idx < 4 * (P_ / 4); idx += 128) {
        int bb = idx / (P_ / 4), pq = idx - bb * (P_ / 4);
        float4 s;
        if (MODE == 0) {
            size_t off = (size_t)(b0 + bb) * P_;
            float4 v0 = ((const float4*)(g_xbar[0] + off))[pq];
            float4 v1 = ((const float4*)(g_xbar[1] + off))[pq];
            float4 v2 = ((const float4*)(g_xbar[2] + off))[pq];
            float4 v3 = ((const float4*)(g_xbar[3] + off))[pq];
            s.x = (v0.x + v1.x) + (v2.x + v3.x);
            s.y = (v0.y + v1.y) + (v2.y + v3.y);
            s.z = (v0.z + v1.z) + (v2.z + v3.z);
            s.w = (v0.w + v1.w) + (v2.w + v3.w);
        } else {
            size_t off = ((size_t)(b0 + bb) * NC_ + i) * P_;
            float4 v0 = ((const float4*)(g_yp[0] + off))[pq];
            float4 v1 = ((const float4*)(g_yp[1] + off))[pq];
            float4 v2 = ((const float4*)(g_yp[2] + off))[pq];
            float4 v3 = ((const float4*)(g_yp[3] + off))[pq];
            s.x = (v0.x + v1.x) + (v2.x + v3.x);
            s.y = (v0.y + v1.y) + (v2.y + v3.y);
            s.z = (v0.z + v1.z) + (v2.z + v3.z);
            s.w = (v0.w + v1.w) + (v2.w + v3.w);
        }
        ((float4*)ys[bb])[pq] = s;
    }
    __syncthreads();

    int w = threadIdx.x >> 5, l = threadIdx.x & 31;
    int b = b0 + w;
    int qk = l & 15, pofs = l >> 4;
    const float* wb = W + i * DC_ + 4 * qk;

    float4 A = make_float4(0.f, 0.f, 0.f, 0.f);
    float4 Bc = make_float4(0.f, 0.f, 0.f, 0.f);
    #pragma unroll 4
    for (int p0 = 0; p0 < P_; p0 += 4) {
        float y0 = ys[w][p0 + pofs];
        float4 w0 = *(const float4*)(wb + (size_t)(p0 + pofs) * WN_);
        A.x += w0.x * y0; A.y += w0.y * y0; A.z += w0.z * y0; A.w += w0.w * y0;
        float y1 = ys[w][p0 + 2 + pofs];
        float4 w1 = *(const float4*)(wb + (size_t)(p0 + 2 + pofs) * WN_);
        Bc.x += w1.x * y1; Bc.y += w1.y * y1; Bc.z += w1.z * y1; Bc.w += w1.w * y1;
    }
    float4 acc;
    acc.x = A.x + Bc.x; acc.y = A.y + Bc.y; acc.z = A.z + Bc.z; acc.w = A.w + Bc.w;
    acc.x += __shfl_xor_sync(0xffffffffu, acc.x, 16);
    acc.y += __shfl_xor_sync(0xffffffffu, acc.y, 16);
    acc.z += __shfl_xor_sync(0xffffffffu, acc.z, 16);
    acc.w += __shfl_xor_sync(0xffffffffu, acc.w, 16);
    if (MODE == 0) {
        acc.x *= 0.0625f; acc.y *= 0.0625f; acc.z *= 0.0625f; acc.w *= 0.0625f;
    }
    float sq = acc.x * acc.x + acc.y * acc.y + acc.z * acc.z + acc.w * acc.w;
    #pragma unroll
    for (int s = 8; s > 0; s >>= 1) sq += __shfl_xor_sync(0xffffffffu, sq, s);
    float r = rsqrtf(sq + 1e-7f);
    acc.x *= r; acc.y *= r; acc.z *= r; acc.w *= r;

    if (l < 16) {
        size_t ob = ((size_t)b * NC_ + i) * DC_ + 4 * qk;
        *(float4*)(g_o + ob) = acc;
        if (out) *(float4*)(out + ob) = acc;
    }
}

// ---------------- K3: vT[b][ipair][p] = W[p, i*64:].o[b,i,:] ------------------
// grid (pchunk=12, bpair=32), block 256. Warp covers 8 p; 4 lanes per p split k.
__global__ void __launch_bounds__(256) k_v(const float* __restrict__ W) {
    int pc = blockIdx.x;
    int b0 = blockIdx.y * 2;
    __shared__ float4 o4[2][256];   // 2 b x 1024 floats
    for (int idx = threadIdx.x; idx < 512; idx += 256) {
        int bb = idx >> 8, k4 = idx & 255;
        o4[bb][k4] = ((const float4*)(g_o + (size_t)(b0 + bb) * WN_))[k4];
    }
    __syncthreads();
    int w = threadIdx.x >> 5, l = threadIdx.x & 31;
    int pr = l >> 2, kq = l & 3;
    int p = pc * 64 + w * 8 + pr;
    const float4* Wp = (const float4*)W + (size_t)p * 256;

    ull acc[2][16];
    #pragma unroll
    for (int bb = 0; bb < 2; bb++)
        #pragma unroll
        for (int i = 0; i < 16; i++) acc[bb][i] = 0ull;

    #pragma unroll
    for (int i = 0; i < 16; i++) {
        #pragma unroll
        for (int s = 0; s < 4; s++) {
            float4 wq = Wp[i * 16 + kq + 4 * s];
            ull wlo = packf2(wq.x, wq.y), whi = packf2(wq.z, wq.w);
            #pragma unroll
            for (int bb = 0; bb < 2; bb++) {
                float4 oq = o4[bb][i * 16 + kq + 4 * s];
                acc[bb][i] = ffma2(wlo, packf2(oq.x, oq.y), acc[bb][i]);
                acc[bb][i] = ffma2(whi, packf2(oq.z, oq.w), acc[bb][i]);
            }
        }
    }
    #pragma unroll
    for (int bb = 0; bb < 2; bb++) {
        float res[16];
        #pragma unroll
        for (int i = 0; i < 16; i++) {
            float2 f = unpack2(acc[bb][i]);
            float s = f.x + f.y;
            s += __shfl_xor_sync(0xffffffffu, s, 1);
            s += __shfl_xor_sync(0xffffffffu, s, 2);
            res[i] = s;
        }
        if (kq == 0) {
            #pragma unroll
            for (int q = 0; q < 8; q++)
                g_vT[b0 + bb][q][p] = make_float2(res[2 * q], res[2 * q + 1]);
        }
    }
}

// ---------------- K4: fused route (GEMM+softmax) + y partials ------------------
// grid (jc=4, b=64), block 256, dynamic smem 82944B.
// Route: tile GEMM logits[128j,16i] = x[128j,768p] . v[768p,16i]
//   thread (tj=t&31, ti=t>>5): 4 consecutive j (4tj..4tj+3), i-pair 2ti.
//   xs staged transposed [k=32][j=128 pad 132]; vsT [ipair=8][768] float2.
// Softmax over i -> cs[128][16] in smem. Y: thread owns p {t,t+256,t+512}.
#define RT_VS  (8 * P_ * 8)          // 49152
#define RT_XS  (32 * 132 * 4)        // 16896
#define RT_PBL (128 * 17 * 4)        // 8704
#define RT_CS  (128 * 4 * 16)        // 8192
#define RT_SMEM (RT_VS + RT_XS + RT_PBL + RT_CS)

__global__ void __launch_bounds__(256) k_routey(const float* __restrict__ x) {
    extern __shared__ char sm[];
    float2* vsT = (float2*)sm;                         // [8][768]
    float*  xs  = (float*)(sm + RT_VS);                // [32][132]
    float*  pbl = (float*)(sm + RT_VS + RT_XS);        // [128][17]
    float4* cs  = (float4*)(sm + RT_VS + RT_XS + RT_PBL); // [128][4]

    int b  = blockIdx.y;
    int jc = blockIdx.x;
    int j0 = jc * 128;
    int t  = threadIdx.x;

    const float2* vsrc = &g_vT[b][0][0];
    for (int idx = t; idx < 8 * P_; idx += 256) vsT[idx] = vsrc[idx];

    int tj = t & 31, ti = t >> 5;
    ull acc[4] = {0ull, 0ull, 0ull, 0ull};
    const float* xb = x + ((size_t)b * J_ + j0) * P_;

    for (int kt = 0; kt < 24; kt++) {
        __syncthreads();
        #pragma unroll
        for (int s = 0; s < 4; s++) {
            int fidx = t + 256 * s;
            int j = fidx >> 3, q = fidx & 7;
            float4 xq = ((const float4*)(xb + (size_t)j * P_ + kt * 32))[q];
            xs[(4 * q + 0) * 132 + j] = xq.x;
            xs[(4 * q + 1) * 132 + j] = xq.y;
            xs[(4 * q + 2) * 132 + j] = xq.z;
            xs[(4 * q + 3) * 132 + j] = xq.w;
        }
        __syncthreads();
        const ulonglong2* vrow = (const ulonglong2*)&vsT[ti * P_ + kt * 32];
        #pragma unroll
        for (int k4 = 0; k4 < 8; k4++) {
            ulonglong2 v01 = vrow[2 * k4];
            ulonglong2 v23 = vrow[2 * k4 + 1];
            float4 x0 = *(const float4*)&xs[(4 * k4 + 0) * 132 + 4 * tj];
            float4 x1 = *(const float4*)&xs[(4 * k4 + 1) * 132 + 4 * tj];
            float4 x2 = *(const float4*)&xs[(4 * k4 + 2) * 132 + 4 * tj];
            float4 x3 = *(const float4*)&xs[(4 * k4 + 3) * 132 + 4 * tj];
            acc[0] = ffma2(pack2(x0.x), v01.x, acc[0]);
            acc[1] = ffma2(pack2(x0.y), v01.x, acc[1]);
            acc[2] = ffma2(pack2(x0.z), v01.x, acc[2]);
            acc[3] = ffma2(pack2(x0.w), v01.x, acc[3]);
            acc[0] = ffma2(pack2(x1.x), v01.y, acc[0]);
            acc[1] = ffma2(pack2(x1.y), v01.y, acc[1]);
            acc[2] = ffma2(pack2(x1.z), v01.y, acc[2]);
            acc[3] = ffma2(pack2(x1.w), v01.y, acc[3]);
            acc[0] = ffma2(pack2(x2.x), v23.x, acc[0]);
            acc[1] = ffma2(pack2(x2.y), v23.x, acc[1]);
            acc[2] = ffma2(pack2(x2.z), v23.x, acc[2]);
            acc[3] = ffma2(pack2(x2.w), v23.x, acc[3]);
            acc[0] = ffma2(pack2(x3.x), v23.y, acc[0]);
            acc[1] = ffma2(pack2(x3.y), v23.y, acc[1]);
            acc[2] = ffma2(pack2(x3.z), v23.y, acc[2]);
            acc[3] = ffma2(pack2(x3.w), v23.y, acc[3]);
        }
    }
    #pragma unroll
    for (int r = 0; r < 4; r++) {
        float2 f = unpack2(acc[r]);
        pbl[(4 * tj + r) * 17 + 2 * ti]     = f.x;
        pbl[(4 * tj + r) * 17 + 2 * ti + 1] = f.y;
    }
    __syncthreads();
    if (t < 128) {
        float bl[16];
        #pragma unroll
        for (int q = 0; q < 16; q++) bl[q] = pbl[t * 17 + q];
        float m = bl[0];
        #pragma unroll
        for (int q = 1; q < 16; q++) m = fmaxf(m, bl[q]);
        float sum = 0.f;
        #pragma unroll
        for (int q = 0; q < 16; q++) { bl[q] = __expf(bl[q] - m); sum += bl[q]; }
        float inv = 1.0f / sum;
        #pragma unroll
        for (int q = 0; q < 4; q++)
            cs[t * 4 + q] = make_float4(bl[4 * q] * inv, bl[4 * q + 1] * inv,
                                        bl[4 * q + 2] * inv, bl[4 * q + 3] * inv);
    }
    __syncthreads();

    // ---- y phase: thread owns p in {t, t+256, t+512} ----
    ull ya[24];
    #pragma unroll
    for (int q = 0; q < 24; q++) ya[q] = 0ull;

    float p0 = xb[t], p1 = xb[t + 256], p2 = xb[t + 512];
    #pragma unroll 2
    for (int j = 0; j < 128; j++) {
        float n0 = p0, n1 = p1, n2 = p2;
        if (j < 127) {
            const float* xn = xb + (size_t)(j + 1) * P_;
            n0 = xn[t]; n1 = xn[t + 256]; n2 = xn[t + 512];
        }
        ull xx0 = pack2(p0), xx1 = pack2(p1), xx2 = pack2(p2);
        const ulonglong2* crow = (const ulonglong2*)(cs + j * 4);
        ulonglong2 ca = crow[0], cb = crow[1], cc = crow[2], cd = crow[3];
        ull cq[8] = {ca.x, ca.y, cb.x, cb.y, cc.x, cc.y, cd.x, cd.y};
        #pragma unroll
        for (int q = 0; q < 8; q++) {
            ya[q]      = ffma2(xx0, cq[q], ya[q]);
            ya[8 + q]  = ffma2(xx1, cq[q], ya[8 + q]);
            ya[16 + q] = ffma2(xx2, cq[q], ya[16 + q]);
        }
        p0 = n0; p1 = n1; p2 = n2;
    }
    #pragma unroll
    for (int pp = 0; pp < 3; pp++) {
        #pragma unroll
        for (int q = 0; q < 8; q++) {
            float2 f = unpack2(ya[pp * 8 + q]);
            g_yp[jc][((size_t)b * NC_ + 2 * q)     * P_ + pp * 256 + t] = f.x;
            g_yp[jc][((size_t)b * NC_ + 2 * q + 1) * P_ + pp * 256 + t] = f.y;
        }
    }
}

// ---------------- launch ----------------
extern "C" void kernel_launch(void* const* d_in, const int* in_sizes, int n_in,
                              void* d_out, int out_size) {
    const float* x = (const float*)d_in[0];
    const float* W = (const float*)d_in[1];
    if (n_in >= 2 && in_sizes[0] < in_sizes[1]) {
        const float* tmp = x; x = W; W = tmp;
    }
    float* out = (float*)d_out;
    (void)out_size;

    cudaFuncSetAttribute(k_routey, cudaFuncAttributeMaxDynamicSharedMemorySize,
                         RT_SMEM);

    dim3 gsq(16, 16);

    k_colsum<<<dim3(3, 4, 64), 256>>>(x);
    k_sq<0><<<gsq, 128>>>(W, nullptr);

    // iteration 1
    k_v<<<dim3(12, 32), 256>>>(W);
    k_routey<<<dim3(4, 64), 256, RT_SMEM>>>(x);
    k_sq<1><<<gsq, 128>>>(W, nullptr);

    // iteration 2 (final)
    k_v<<<dim3(12, 32), 256>>>(W);
    k_routey<<<dim3(4, 64), 256, RT_SMEM>>>(x);
    k_sq<1><<<gsq, 128>>>(W, out);
}

// round 4
// speedup vs baseline: 1.2114x; 1.0174x over previous
#include <cuda_runtime.h>

#define B_  64
#define J_  512
#define P_  768
#define NC_ 16
#define DC_ 64
#define WN_ 1024   // NC_*DC_

typedef unsigned long long ull;

// ---------------- scratch (device globals; no allocation allowed) ----------------
__device__ float  g_xbar[4][B_ * P_];       // colsum partials [jsplit][b*P+p]
__device__ float2 g_vT[B_][8][P_];          // v transposed    [b][ipair][p]
__device__ float  g_yp[8][B_ * NC_ * P_];   // y partials      [jsplit][b][i][p]

// ---------------- packed f32x2 helpers ----------------
__device__ __forceinline__ ull ffma2(ull a, ull b, ull c) {
    ull d;
    asm("fma.rn.f32x2 %0, %1, %2, %3;" : "=l"(d) : "l"(a), "l"(b), "l"(c));
    return d;
}
__device__ __forceinline__ ull pack2(float v) {
    ull d; unsigned int u = __float_as_uint(v);
    asm("mov.b64 %0, {%1, %1};" : "=l"(d) : "r"(u));
    return d;
}
__device__ __forceinline__ float2 unpack2(ull u) {
    float2 f;
    f.x = __uint_as_float((unsigned int)u);
    f.y = __uint_as_float((unsigned int)(u >> 32));
    return f;
}

// ---------------- K1: xbar partials (reads x once, coalesced) ----------------
__global__ void k_colsum(const float* __restrict__ x) {
    int p  = blockIdx.x * 256 + threadIdx.x;
    int js = blockIdx.y;
    int b  = blockIdx.z;
    const float* xp = x + ((size_t)b * J_ + (size_t)js * 128) * P_ + p;
    float a0 = 0.f, a1 = 0.f, a2 = 0.f, a3 = 0.f;
    #pragma unroll 8
    for (int j = 0; j < 128; j += 4) {
        a0 += xp[(size_t)(j + 0) * P_];
        a1 += xp[(size_t)(j + 1) * P_];
        a2 += xp[(size_t)(j + 2) * P_];
        a3 += xp[(size_t)(j + 3) * P_];
    }
    g_xbar[js][b * P_ + p] = (a0 + a1) + (a2 + a3);
}

// ---------------- K2: s = src @ W_i, squash, fused v-projection ---------------
// MODE 0: src = sum of xbar partials (uniform c => scale 1/16)
// MODE 1: src = sum of 8 y partials [b][i][p]
// grid (i=16, bgroup=16), block 128 (warp w -> b = b0+w).
template <int MODE, bool DO_V>
__global__ void __launch_bounds__(128) k_sqv(const float* __restrict__ W,
                                             float* __restrict__ out) {
    int i  = blockIdx.x;
    int b0 = blockIdx.y * 4;
    __shared__ float ys[4][P_];
    for (int idx = threadIdx.x; idx < 4 * (P_ / 4); idx += 128) {
        int bb = idx / (P_ / 4), pq = idx - bb * (P_ / 4);
        float4 s;
        if (MODE == 0) {
            size_t off = (size_t)(b0 + bb) * P_;
            float4 v0 = ((const float4*)(g_xbar[0] + off))[pq];
            float4 v1 = ((const float4*)(g_xbar[1] + off))[pq];
            float4 v2 = ((const float4*)(g_xbar[2] + off))[pq];
            float4 v3 = ((const float4*)(g_xbar[3] + off))[pq];
            s.x = (v0.x + v1.x) + (v2.x + v3.x);
            s.y = (v0.y + v1.y) + (v2.y + v3.y);
            s.z = (v0.z + v1.z) + (v2.z + v3.z);
            s.w = (v0.w + v1.w) + (v2.w + v3.w);
        } else {
            size_t off = ((size_t)(b0 + bb) * NC_ + i) * P_;
            s = make_float4(0.f, 0.f, 0.f, 0.f);
            #pragma unroll
            for (int sp = 0; sp < 8; sp++) {
                float4 v = ((const float4*)(g_yp[sp] + off))[pq];
                s.x += v.x; s.y += v.y; s.z += v.z; s.w += v.w;
            }
        }
        ((float4*)ys[bb])[pq] = s;
    }
    __syncthreads();

    int w = threadIdx.x >> 5, l = threadIdx.x & 31;
    int b = b0 + w;
    int qk = l & 15, pofs = l >> 4;
    const float* wb = W + i * DC_ + 4 * qk;

    float4 A = make_float4(0.f, 0.f, 0.f, 0.f);
    float4 Bc = make_float4(0.f, 0.f, 0.f, 0.f);
    #pragma unroll 4
    for (int p0 = 0; p0 < P_; p0 += 4) {
        float y0 = ys[w][p0 + pofs];
        float4 w0 = *(const float4*)(wb + (size_t)(p0 + pofs) * WN_);
        A.x += w0.x * y0; A.y += w0.y * y0; A.z += w0.z * y0; A.w += w0.w * y0;
        float y1 = ys[w][p0 + 2 + pofs];
        float4 w1 = *(const float4*)(wb + (size_t)(p0 + 2 + pofs) * WN_);
        Bc.x += w1.x * y1; Bc.y += w1.y * y1; Bc.z += w1.z * y1; Bc.w += w1.w * y1;
    }
    float4 acc;
    acc.x = A.x + Bc.x; acc.y = A.y + Bc.y; acc.z = A.z + Bc.z; acc.w = A.w + Bc.w;
    acc.x += __shfl_xor_sync(0xffffffffu, acc.x, 16);
    acc.y += __shfl_xor_sync(0xffffffffu, acc.y, 16);
    acc.z += __shfl_xor_sync(0xffffffffu, acc.z, 16);
    acc.w += __shfl_xor_sync(0xffffffffu, acc.w, 16);
    if (MODE == 0) {
        acc.x *= 0.0625f; acc.y *= 0.0625f; acc.z *= 0.0625f; acc.w *= 0.0625f;
    }
    float sq = acc.x * acc.x + acc.y * acc.y + acc.z * acc.z + acc.w * acc.w;
    #pragma unroll
    for (int s = 8; s > 0; s >>= 1) sq += __shfl_xor_sync(0xffffffffu, sq, s);
    float r = rsqrtf(sq + 1e-7f);
    acc.x *= r; acc.y *= r; acc.z *= r; acc.w *= r;

    if (out != nullptr && l < 16)
        *(float4*)(out + ((size_t)b * NC_ + i) * DC_ + 4 * qk) = acc;

    if (DO_V) {
        // redistribute o: lane (pr=l>>2, kq=l&3) needs o[16s+4kq+c]
        int kq = l & 3, pr = l >> 2;
        float ok[4][4];
        #pragma unroll
        for (int s = 0; s < 4; s++) {
            int src = kq + 4 * s;   // lane holding k-quad (16s+4kq)/4
            ok[s][0] = __shfl_sync(0xffffffffu, acc.x, src);
            ok[s][1] = __shfl_sync(0xffffffffu, acc.y, src);
            ok[s][2] = __shfl_sync(0xffffffffu, acc.z, src);
            ok[s][3] = __shfl_sync(0xffffffffu, acc.w, src);
        }
        float* vout = (float*)g_vT;
        size_t vbase = ((size_t)b * 8 + (i >> 1)) * (size_t)(P_ * 2) + (i & 1);
        #pragma unroll 4
        for (int p0 = 0; p0 < P_; p0 += 8) {
            int p = p0 + pr;
            const float4* wr = (const float4*)(W + (size_t)p * WN_ + i * DC_);
            float sa = 0.f;
            #pragma unroll
            for (int s = 0; s < 4; s++) {
                float4 wq = wr[kq + 4 * s];   // k = 4kq+16s..+3
                sa += wq.x * ok[s][0] + wq.y * ok[s][1]
                    + wq.z * ok[s][2] + wq.w * ok[s][3];
            }
            sa += __shfl_xor_sync(0xffffffffu, sa, 1);
            sa += __shfl_xor_sync(0xffffffffu, sa, 2);
            if (kq == 0) vout[vbase + (size_t)p * 2] = sa;
        }
    }
}

// ---------------- K3: fused route (slab GEMM + softmax) + y partials ----------
// grid (jc=8, b=64), block 256 (8 warps = 8 k-slices of 16 within a 128-k slab).
// Thread (w, tj=l&7, ti=l>>3): 8 j (tj*8..+7) x 2 ipairs (2ti,2ti+1), 16 k/slab.
// Partial logits merged via shared atomicAdd into padded pbl[64][17].
#define RY_XS   (128 * 68 * 4)     // 34816  xs[k][68]
#define RY_VT   (128 * 8 * 8)      //  8192  vt[k][8] float2
#define RY_PBL  (64 * 17 * 4)      //  4352
#define RY_CS   (64 * 4 * 16)      //  4096  cs[j][4] float4
#define RY_SMEM (RY_XS + RY_VT + RY_PBL + RY_CS)

__global__ void __launch_bounds__(256, 4) k_routey(const float* __restrict__ x) {
    extern __shared__ char sm[];
    float*  xs  = (float*)sm;
    float2* vt  = (float2*)(sm + RY_XS);
    float*  pbl = (float*)(sm + RY_XS + RY_VT);
    float4* cs  = (float4*)(sm + RY_XS + RY_VT + RY_PBL);

    int b  = blockIdx.y;
    int jc = blockIdx.x;
    const float* xb = x + ((size_t)b * J_ + jc * 64) * P_;
    int t = threadIdx.x, w = t >> 5, l = t & 31;
    int tj = l & 7, ti = l >> 3;

    for (int idx = t; idx < 64 * 17; idx += 256) pbl[idx] = 0.f;

    ull acc[16];
    #pragma unroll
    for (int q = 0; q < 16; q++) acc[q] = 0ull;

    const float2* vsrc = &g_vT[b][0][0];   // [ip][768]

    for (int s = 0; s < 6; s++) {
        __syncthreads();
        // stage xs (transposed [k][j], pitch 68)
        #pragma unroll
        for (int q = 0; q < 8; q++) {
            int m  = q * 8 + w;
            int j  = (m & 15) * 4 + (l & 3);
            int kq = (m >> 4) * 8 + (l >> 2);
            float4 xv = ((const float4*)(xb + (size_t)j * P_ + 128 * s))[kq];
            int kk = 4 * kq;
            xs[(kk + 0) * 68 + j] = xv.x;
            xs[(kk + 1) * 68 + j] = xv.y;
            xs[(kk + 2) * 68 + j] = xv.z;
            xs[(kk + 3) * 68 + j] = xv.w;
        }
        // stage vt [k][ipair]
        #pragma unroll
        for (int q = 0; q < 4; q++) {
            int e = q * 256 + t;
            int ip = e >> 7, k = e & 127;
            vt[k * 8 + ip] = vsrc[(size_t)ip * P_ + 128 * s + k];
        }
        __syncthreads();
        // compute: this warp's k sub-range [16w, 16w+16)
        #pragma unroll
        for (int kk = 0; kk < 16; kk++) {
            int k = 16 * w + kk;
            float4 xa = *(const float4*)&xs[k * 68 + tj * 8];
            float4 xc = *(const float4*)&xs[k * 68 + tj * 8 + 4];
            ulonglong2 vv = *(const ulonglong2*)&vt[k * 8 + 2 * ti];
            acc[0]  = ffma2(pack2(xa.x), vv.x, acc[0]);
            acc[1]  = ffma2(pack2(xa.x), vv.y, acc[1]);
            acc[2]  = ffma2(pack2(xa.y), vv.x, acc[2]);
            acc[3]  = ffma2(pack2(xa.y), vv.y, acc[3]);
            acc[4]  = ffma2(pack2(xa.z), vv.x, acc[4]);
            acc[5]  = ffma2(pack2(xa.z), vv.y, acc[5]);
            acc[6]  = ffma2(pack2(xa.w), vv.x, acc[6]);
            acc[7]  = ffma2(pack2(xa.w), vv.y, acc[7]);
            acc[8]  = ffma2(pack2(xc.x), vv.x, acc[8]);
            acc[9]  = ffma2(pack2(xc.x), vv.y, acc[9]);
            acc[10] = ffma2(pack2(xc.y), vv.x, acc[10]);
            acc[11] = ffma2(pack2(xc.y), vv.y, acc[11]);
            acc[12] = ffma2(pack2(xc.z), vv.x, acc[12]);
            acc[13] = ffma2(pack2(xc.z), vv.y, acc[13]);
            acc[14] = ffma2(pack2(xc.w), vv.x, acc[14]);
            acc[15] = ffma2(pack2(xc.w), vv.y, acc[15]);
        }
    }
    __syncthreads();
    // merge k-slice partial logits
    #pragma unroll
    for (int jj = 0; jj < 8; jj++) {
        int j = tj * 8 + jj;
        float2 f0 = unpack2(acc[jj * 2 + 0]);
        float2 f1 = unpack2(acc[jj * 2 + 1]);
        atomicAdd(&pbl[j * 17 + 4 * ti + 0], f0.x);
        atomicAdd(&pbl[j * 17 + 4 * ti + 1], f0.y);
        atomicAdd(&pbl[j * 17 + 4 * ti + 2], f1.x);
        atomicAdd(&pbl[j * 17 + 4 * ti + 3], f1.y);
    }
    __syncthreads();
    if (t < 64) {
        float bl[16];
        #pragma unroll
        for (int q = 0; q < 16; q++) bl[q] = pbl[t * 17 + q];
        float m = bl[0];
        #pragma unroll
        for (int q = 1; q < 16; q++) m = fmaxf(m, bl[q]);
        float sum = 0.f;
        #pragma unroll
        for (int q = 0; q < 16; q++) { bl[q] = __expf(bl[q] - m); sum += bl[q]; }
        float inv = 1.0f / sum;
        #pragma unroll
        for (int q = 0; q < 4; q++)
            cs[t * 4 + q] = make_float4(bl[4 * q] * inv, bl[4 * q + 1] * inv,
                                        bl[4 * q + 2] * inv, bl[4 * q + 3] * inv);
    }
    __syncthreads();

    // ---- y phase: thread owns p in {t, t+256, t+512}, all 16 i ----
    ull ya[24];
    #pragma unroll
    for (int q = 0; q < 24; q++) ya[q] = 0ull;

    for (int j = 0; j < 64; j++) {
        float p0 = xb[(size_t)j * P_ + t];
        float p1 = xb[(size_t)j * P_ + t + 256];
        float p2 = xb[(size_t)j * P_ + t + 512];
        ull x0 = pack2(p0), x1 = pack2(p1), x2 = pack2(p2);
        const ulonglong2* crow = (const ulonglong2*)(cs + j * 4);
        ulonglong2 ca = crow[0];
        ya[0]  = ffma2(x0, ca.x, ya[0]);  ya[8]  = ffma2(x1, ca.x, ya[8]);  ya[16] = ffma2(x2, ca.x, ya[16]);
        ya[1]  = ffma2(x0, ca.y, ya[1]);  ya[9]  = ffma2(x1, ca.y, ya[9]);  ya[17] = ffma2(x2, ca.y, ya[17]);
        ulonglong2 cb2 = crow[1];
        ya[2]  = ffma2(x0, cb2.x, ya[2]); ya[10] = ffma2(x1, cb2.x, ya[10]); ya[18] = ffma2(x2, cb2.x, ya[18]);
        ya[3]  = ffma2(x0, cb2.y, ya[3]); ya[11] = ffma2(x1, cb2.y, ya[11]); ya[19] = ffma2(x2, cb2.y, ya[19]);
        ulonglong2 cc = crow[2];
        ya[4]  = ffma2(x0, cc.x, ya[4]);  ya[12] = ffma2(x1, cc.x, ya[12]); ya[20] = ffma2(x2, cc.x, ya[20]);
        ya[5]  = ffma2(x0, cc.y, ya[5]);  ya[13] = ffma2(x1, cc.y, ya[13]); ya[21] = ffma2(x2, cc.y, ya[21]);
        ulonglong2 cd = crow[3];
        ya[6]  = ffma2(x0, cd.x, ya[6]);  ya[14] = ffma2(x1, cd.x, ya[14]); ya[22] = ffma2(x2, cd.x, ya[22]);
        ya[7]  = ffma2(x0, cd.y, ya[7]);  ya[15] = ffma2(x1, cd.y, ya[15]); ya[23] = ffma2(x2, cd.y, ya[23]);
    }
    #pragma unroll
    for (int pp = 0; pp < 3; pp++) {
        #pragma unroll
        for (int q = 0; q < 8; q++) {
            float2 f = unpack2(ya[pp * 8 + q]);
            g_yp[jc][((size_t)b * NC_ + 2 * q)     * P_ + pp * 256 + t] = f.x;
            g_yp[jc][((size_t)b * NC_ + 2 * q + 1) * P_ + pp * 256 + t] = f.y;
        }
    }
}

// ---------------- launch ----------------
extern "C" void kernel_launch(void* const* d_in, const int* in_sizes, int n_in,
                              void* d_out, int out_size) {
    const float* x = (const float*)d_in[0];
    const float* W = (const float*)d_in[1];
    if (n_in >= 2 && in_sizes[0] < in_sizes[1]) {
        const float* tmp = x; x = W; W = tmp;
    }
    float* out = (float*)d_out;
    (void)out_size;

    cudaFuncSetAttribute(k_routey, cudaFuncAttributeMaxDynamicSharedMemorySize,
                         RY_SMEM);

    dim3 gsq(16, 16);

    k_colsum<<<dim3(3, 4, 64), 256>>>(x);
    k_sqv<0, true><<<gsq, 128>>>(W, nullptr);

    // iteration 1
    k_routey<<<dim3(8, 64), 256, RY_SMEM>>>(x);
    k_sqv<1, true><<<gsq, 128>>>(W, nullptr);

    // iteration 2 (final)
    k_routey<<<dim3(8, 64), 256, RY_SMEM>>>(x);
    k_sqv<1, false><<<gsq, 128>>>(W, out);
}

// round 5
// speedup vs baseline: 1.3902x; 1.1476x over previous
#include <cuda_runtime.h>

#define B_  64
#define J_  512
#define P_  768
#define NC_ 16
#define DC_ 64
#define WN_ 1024   // NC_*DC_

typedef unsigned long long ull;

// ---------------- scratch (device globals; no allocation allowed) ----------------
__device__ float  g_xbar[4][B_ * P_];       // colsum partials [jsplit][b*P+p]
__device__ float  g_o[B_ * WN_];            // routed outputs  [b][i*64+k]
__device__ float2 g_vT[B_][8][P_];          // v transposed    [b][ipair][p]
__device__ float  g_yp[8][B_ * NC_ * P_];   // y partials      [jsplit][b][i][p]

// ---------------- packed f32x2 helpers ----------------
__device__ __forceinline__ ull ffma2(ull a, ull b, ull c) {
    ull d;
    asm("fma.rn.f32x2 %0, %1, %2, %3;" : "=l"(d) : "l"(a), "l"(b), "l"(c));
    return d;
}
__device__ __forceinline__ ull pack2(float v) {
    ull d; unsigned int u = __float_as_uint(v);
    asm("mov.b64 %0, {%1, %1};" : "=l"(d) : "r"(u));
    return d;
}
__device__ __forceinline__ float2 unpack2(ull u) {
    float2 f;
    f.x = __uint_as_float((unsigned int)u);
    f.y = __uint_as_float((unsigned int)(u >> 32));
    return f;
}

// ---------------- K1: xbar partials (reads x once, coalesced) ----------------
__global__ void k_colsum(const float* __restrict__ x) {
    int p  = blockIdx.x * 256 + threadIdx.x;
    int js = blockIdx.y;
    int b  = blockIdx.z;
    const float* xp = x + ((size_t)b * J_ + (size_t)js * 128) * P_ + p;
    float a0 = 0.f, a1 = 0.f, a2 = 0.f, a3 = 0.f;
    #pragma unroll 8
    for (int j = 0; j < 128; j += 4) {
        a0 += xp[(size_t)(j + 0) * P_];
        a1 += xp[(size_t)(j + 1) * P_];
        a2 += xp[(size_t)(j + 2) * P_];
        a3 += xp[(size_t)(j + 3) * P_];
    }
    g_xbar[js][b * P_ + p] = (a0 + a1) + (a2 + a3);
}

// ---------------- K2: s = src @ W_i, squash -> g_o (and out at final) ---------
// MODE 0: src = sum of 4 xbar partials (uniform c => scale 1/16)
// MODE 1: src = sum of 8 y partials [b][i][p]
// grid (i=16, bg=16), block 256 = 8 warps: warp w -> (b = w&3, phalf = w>>2).
// Lane l owns k = {2l, 2l+1} via float2 W loads (256B/warp = 2 lines).
template <int MODE>
__global__ void __launch_bounds__(256) k_s(const float* __restrict__ W,
                                           float* __restrict__ out) {
    int i  = blockIdx.x;
    int b0 = blockIdx.y * 4;
    __shared__ float  ys[4][P_];
    __shared__ float2 ss[8][32];
    for (int idx = threadIdx.x; idx < 4 * (P_ / 4); idx += 256) {
        int bb = idx / (P_ / 4), pq = idx - bb * (P_ / 4);
        float4 s;
        if (MODE == 0) {
            size_t off = (size_t)(b0 + bb) * P_;
            float4 v0 = ((const float4*)(g_xbar[0] + off))[pq];
            float4 v1 = ((const float4*)(g_xbar[1] + off))[pq];
            float4 v2 = ((const float4*)(g_xbar[2] + off))[pq];
            float4 v3 = ((const float4*)(g_xbar[3] + off))[pq];
            s.x = (v0.x + v1.x) + (v2.x + v3.x);
            s.y = (v0.y + v1.y) + (v2.y + v3.y);
            s.z = (v0.z + v1.z) + (v2.z + v3.z);
            s.w = (v0.w + v1.w) + (v2.w + v3.w);
        } else {
            size_t off = ((size_t)(b0 + bb) * NC_ + i) * P_;
            s = make_float4(0.f, 0.f, 0.f, 0.f);
            #pragma unroll
            for (int sp = 0; sp < 8; sp++) {
                float4 v = ((const float4*)(g_yp[sp] + off))[pq];
                s.x += v.x; s.y += v.y; s.z += v.z; s.w += v.w;
            }
        }
        ((float4*)ys[bb])[pq] = s;
    }
    __syncthreads();

    int w = threadIdx.x >> 5, l = threadIdx.x & 31;
    int bb = w & 3, ph = w >> 2;
    const float* yrow = ys[bb] + ph * 384;
    const float* wrow = W + ((size_t)ph * 384) * WN_ + i * DC_ + 2 * l;

    float2 a0 = make_float2(0.f, 0.f), a1 = a0, a2 = a0, a3 = a0;
    #pragma unroll 4
    for (int p = 0; p < 384; p += 4) {
        float2 w0 = *(const float2*)(wrow + (size_t)(p + 0) * WN_);
        float2 w1 = *(const float2*)(wrow + (size_t)(p + 1) * WN_);
        float2 w2 = *(const float2*)(wrow + (size_t)(p + 2) * WN_);
        float2 w3 = *(const float2*)(wrow + (size_t)(p + 3) * WN_);
        float y0 = yrow[p], y1 = yrow[p + 1], y2 = yrow[p + 2], y3 = yrow[p + 3];
        a0.x += w0.x * y0; a0.y += w0.y * y0;
        a1.x += w1.x * y1; a1.y += w1.y * y1;
        a2.x += w2.x * y2; a2.y += w2.y * y2;
        a3.x += w3.x * y3; a3.y += w3.y * y3;
    }
    float2 a;
    a.x = (a0.x + a1.x) + (a2.x + a3.x);
    a.y = (a0.y + a1.y) + (a2.y + a3.y);
    ss[w][l] = a;
    __syncthreads();

    if (w < 4) {
        float2 p0 = ss[w][l], p1 = ss[w + 4][l];
        float2 s2 = make_float2(p0.x + p1.x, p0.y + p1.y);
        if (MODE == 0) { s2.x *= 0.0625f; s2.y *= 0.0625f; }
        float sq = s2.x * s2.x + s2.y * s2.y;
        #pragma unroll
        for (int s = 16; s > 0; s >>= 1) sq += __shfl_xor_sync(0xffffffffu, sq, s);
        float r = rsqrtf(sq + 1e-7f);
        s2.x *= r; s2.y *= r;
        size_t ob = ((size_t)(b0 + w) * NC_ + i) * DC_ + 2 * l;
        *(float2*)(g_o + ob) = s2;
        if (out) *(float2*)(out + ob) = s2;
    }
}

// ---------------- K3: vT[b][ip][p] = (W[p,2ip*64:].o, W[p,(2ip+1)*64:].o) -----
// grid (pc=48, bg=16), block 128. W tile [16p x 1024] staged in smem with a
// 16B xor swizzle; thread (p=t&15, ip=t>>4) owns full 64-k dots for 4 b.
__global__ void __launch_bounds__(128) k_v(const float* __restrict__ W) {
    int pc = blockIdx.x * 16;
    int bg = blockIdx.y * 4;
    __shared__ float4 ws[16 * 256];   // 64KB, swizzled
    __shared__ float4 os[4][256];     // 16KB
    int t = threadIdx.x;

    for (int idx = t; idx < 4 * 256; idx += 128) {
        int bb = idx >> 8, q = idx & 255;
        os[bb][q] = ((const float4*)(g_o + (size_t)(bg + bb) * WN_))[q];
    }
    for (int idx = t; idx < 16 * 256; idx += 128) {
        int p = idx >> 8, q = idx & 255;
        float4 wv = ((const float4*)(W + (size_t)(pc + p) * WN_))[q];
        int qs = (q & ~15) | ((q & 15) ^ p);
        ws[p * 256 + qs] = wv;
    }
    __syncthreads();

    int p = t & 15, ip = t >> 4;      // ip in 0..7
    float ax[4] = {0.f, 0.f, 0.f, 0.f};
    float ay[4] = {0.f, 0.f, 0.f, 0.f};
    #pragma unroll
    for (int qq = 0; qq < 32; qq++) {
        int q  = ip * 32 + qq;
        int qs = (q & ~15) | ((q & 15) ^ p);
        float4 wv = ws[p * 256 + qs];
        #pragma unroll
        for (int bb = 0; bb < 4; bb++) {
            float4 ov = os[bb][q];
            float d = wv.x * ov.x + wv.y * ov.y + wv.z * ov.z + wv.w * ov.w;
            if (qq < 16) ax[bb] += d; else ay[bb] += d;
        }
    }
    #pragma unroll
    for (int bb = 0; bb < 4; bb++)
        g_vT[bg + bb][ip][pc + p] = make_float2(ax[bb], ay[bb]);
}

// ---------------- K4: fused route (slab GEMM + softmax) + y partials ----------
#define RY_XS   (128 * 68 * 4)     // 34816  xs[k][68]
#define RY_VT   (128 * 8 * 8)      //  8192  vt[k][8] float2
#define RY_PBL  (64 * 17 * 4)      //  4352
#define RY_CS   (64 * 4 * 16)      //  4096  cs[j][4] float4
#define RY_SMEM (RY_XS + RY_VT + RY_PBL + RY_CS)

__global__ void __launch_bounds__(256, 4) k_routey(const float* __restrict__ x) {
    extern __shared__ char sm[];
    float*  xs  = (float*)sm;
    float2* vt  = (float2*)(sm + RY_XS);
    float*  pbl = (float*)(sm + RY_XS + RY_VT);
    float4* cs  = (float4*)(sm + RY_XS + RY_VT + RY_PBL);

    int b  = blockIdx.y;
    int jc = blockIdx.x;
    const float* xb = x + ((size_t)b * J_ + jc * 64) * P_;
    int t = threadIdx.x, w = t >> 5, l = t & 31;
    int tj = l & 7, ti = l >> 3;

    for (int idx = t; idx < 64 * 17; idx += 256) pbl[idx] = 0.f;

    ull acc[16];
    #pragma unroll
    for (int q = 0; q < 16; q++) acc[q] = 0ull;

    const float2* vsrc = &g_vT[b][0][0];   // [ip][768]

    for (int s = 0; s < 6; s++) {
        __syncthreads();
        #pragma unroll
        for (int q = 0; q < 8; q++) {
            int m  = q * 8 + w;
            int j  = (m & 15) * 4 + (l & 3);
            int kq = (m >> 4) * 8 + (l >> 2);
            float4 xv = ((const float4*)(xb + (size_t)j * P_ + 128 * s))[kq];
            int kk = 4 * kq;
            xs[(kk + 0) * 68 + j] = xv.x;
            xs[(kk + 1) * 68 + j] = xv.y;
            xs[(kk + 2) * 68 + j] = xv.z;
            xs[(kk + 3) * 68 + j] = xv.w;
        }
        #pragma unroll
        for (int q = 0; q < 4; q++) {
            int e = q * 256 + t;
            int ip = e >> 7, k = e & 127;
            vt[k * 8 + ip] = vsrc[(size_t)ip * P_ + 128 * s + k];
        }
        __syncthreads();
        #pragma unroll
        for (int kk = 0; kk < 16; kk++) {
            int k = 16 * w + kk;
            float4 xa = *(const float4*)&xs[k * 68 + tj * 8];
            float4 xc = *(const float4*)&xs[k * 68 + tj * 8 + 4];
            ulonglong2 vv = *(const ulonglong2*)&vt[k * 8 + 2 * ti];
            acc[0]  = ffma2(pack2(xa.x), vv.x, acc[0]);
            acc[1]  = ffma2(pack2(xa.x), vv.y, acc[1]);
            acc[2]  = ffma2(pack2(xa.y), vv.x, acc[2]);
            acc[3]  = ffma2(pack2(xa.y), vv.y, acc[3]);
            acc[4]  = ffma2(pack2(xa.z), vv.x, acc[4]);
            acc[5]  = ffma2(pack2(xa.z), vv.y, acc[5]);
            acc[6]  = ffma2(pack2(xa.w), vv.x, acc[6]);
            acc[7]  = ffma2(pack2(xa.w), vv.y, acc[7]);
            acc[8]  = ffma2(pack2(xc.x), vv.x, acc[8]);
            acc[9]  = ffma2(pack2(xc.x), vv.y, acc[9]);
            acc[10] = ffma2(pack2(xc.y), vv.x, acc[10]);
            acc[11] = ffma2(pack2(xc.y), vv.y, acc[11]);
            acc[12] = ffma2(pack2(xc.z), vv.x, acc[12]);
            acc[13] = ffma2(pack2(xc.z), vv.y, acc[13]);
            acc[14] = ffma2(pack2(xc.w), vv.x, acc[14]);
            acc[15] = ffma2(pack2(xc.w), vv.y, acc[15]);
        }
    }
    __syncthreads();
    #pragma unroll
    for (int jj = 0; jj < 8; jj++) {
        int j = tj * 8 + jj;
        float2 f0 = unpack2(acc[jj * 2 + 0]);
        float2 f1 = unpack2(acc[jj * 2 + 1]);
        atomicAdd(&pbl[j * 17 + 4 * ti + 0], f0.x);
        atomicAdd(&pbl[j * 17 + 4 * ti + 1], f0.y);
        atomicAdd(&pbl[j * 17 + 4 * ti + 2], f1.x);
        atomicAdd(&pbl[j * 17 + 4 * ti + 3], f1.y);
    }
    __syncthreads();
    if (t < 64) {
        float bl[16];
        #pragma unroll
        for (int q = 0; q < 16; q++) bl[q] = pbl[t * 17 + q];
        float m = bl[0];
        #pragma unroll
        for (int q = 1; q < 16; q++) m = fmaxf(m, bl[q]);
        float sum = 0.f;
        #pragma unroll
        for (int q = 0; q < 16; q++) { bl[q] = __expf(bl[q] - m); sum += bl[q]; }
        float inv = 1.0f / sum;
        #pragma unroll
        for (int q = 0; q < 4; q++)
            cs[t * 4 + q] = make_float4(bl[4 * q] * inv, bl[4 * q + 1] * inv,
                                        bl[4 * q + 2] * inv, bl[4 * q + 3] * inv);
    }
    __syncthreads();

    ull ya[24];
    #pragma unroll
    for (int q = 0; q < 24; q++) ya[q] = 0ull;

    for (int j = 0; j < 64; j++) {
        float p0 = xb[(size_t)j * P_ + t];
        float p1 = xb[(size_t)j * P_ + t + 256];
        float p2 = xb[(size_t)j * P_ + t + 512];
        ull x0 = pack2(p0), x1 = pack2(p1), x2 = pack2(p2);
        const ulonglong2* crow = (const ulonglong2*)(cs + j * 4);
        ulonglong2 ca = crow[0];
        ya[0]  = ffma2(x0, ca.x, ya[0]);  ya[8]  = ffma2(x1, ca.x, ya[8]);  ya[16] = ffma2(x2, ca.x, ya[16]);
        ya[1]  = ffma2(x0, ca.y, ya[1]);  ya[9]  = ffma2(x1, ca.y, ya[9]);  ya[17] = ffma2(x2, ca.y, ya[17]);
        ulonglong2 cb2 = crow[1];
        ya[2]  = ffma2(x0, cb2.x, ya[2]); ya[10] = ffma2(x1, cb2.x, ya[10]); ya[18] = ffma2(x2, cb2.x, ya[18]);
        ya[3]  = ffma2(x0, cb2.y, ya[3]); ya[11] = ffma2(x1, cb2.y, ya[11]); ya[19] = ffma2(x2, cb2.y, ya[19]);
        ulonglong2 cc = crow[2];
        ya[4]  = ffma2(x0, cc.x, ya[4]);  ya[12] = ffma2(x1, cc.x, ya[12]); ya[20] = ffma2(x2, cc.x, ya[20]);
        ya[5]  = ffma2(x0, cc.y, ya[5]);  ya[13] = ffma2(x1, cc.y, ya[13]); ya[21] = ffma2(x2, cc.y, ya[21]);
        ulonglong2 cd = crow[3];
        ya[6]  = ffma2(x0, cd.x, ya[6]);  ya[14] = ffma2(x1, cd.x, ya[14]); ya[22] = ffma2(x2, cd.x, ya[22]);
        ya[7]  = ffma2(x0, cd.y, ya[7]);  ya[15] = ffma2(x1, cd.y, ya[15]); ya[23] = ffma2(x2, cd.y, ya[23]);
    }
    #pragma unroll
    for (int pp = 0; pp < 3; pp++) {
        #pragma unroll
        for (int q = 0; q < 8; q++) {
            float2 f = unpack2(ya[pp * 8 + q]);
            g_yp[jc][((size_t)b * NC_ + 2 * q)     * P_ + pp * 256 + t] = f.x;
            g_yp[jc][((size_t)b * NC_ + 2 * q + 1) * P_ + pp * 256 + t] = f.y;
        }
    }
}

// ---------------- launch ----------------
extern "C" void kernel_launch(void* const* d_in, const int* in_sizes, int n_in,
                              void* d_out, int out_size) {
    const float* x = (const float*)d_in[0];
    const float* W = (const float*)d_in[1];
    if (n_in >= 2 && in_sizes[0] < in_sizes[1]) {
        const float* tmp = x; x = W; W = tmp;
    }
    float* out = (float*)d_out;
    (void)out_size;

    cudaFuncSetAttribute(k_routey, cudaFuncAttributeMaxDynamicSharedMemorySize,
                         RY_SMEM);
    cudaFuncSetAttribute(k_v, cudaFuncAttributeMaxDynamicSharedMemorySize,
                         96 * 1024);

    dim3 gsq(16, 16);

    k_colsum<<<dim3(3, 4, 64), 256>>>(x);
    k_s<0><<<gsq, 256>>>(W, nullptr);
    k_v<<<dim3(48, 16), 128>>>(W);

    // iteration 1
    k_routey<<<dim3(8, 64), 256, RY_SMEM>>>(x);
    k_s<1><<<gsq, 256>>>(W, nullptr);
    k_v<<<dim3(48, 16), 128>>>(W);

    // iteration 2 (final)
    k_routey<<<dim3(8, 64), 256, RY_SMEM>>>(x);
    k_s<1><<<gsq, 256>>>(W, out);
}

// round 6
// speedup vs baseline: 1.4708x; 1.0580x over previous
#include <cuda_runtime.h>

#define B_  64
#define J_  512
#define P_  768
#define NC_ 16
#define DC_ 64
#define WN_ 1024   // NC_*DC_

typedef unsigned long long ull;

// ---------------- scratch (device globals; no allocation allowed) ----------------
__device__ float  g_xbar[4][B_ * P_];       // colsum partials [jsplit][b*P+p]
__device__ float  g_o[B_ * WN_];            // routed outputs  [b][i*64+k]
__device__ float2 g_vT[B_][8][P_];          // v transposed    [b][ipair][p]
__device__ float  g_yp[8][B_ * NC_ * P_];   // y partials      [jsplit][b][i][p]

// ---------------- packed f32x2 helpers ----------------
__device__ __forceinline__ ull ffma2(ull a, ull b, ull c) {
    ull d;
    asm("fma.rn.f32x2 %0, %1, %2, %3;" : "=l"(d) : "l"(a), "l"(b), "l"(c));
    return d;
}
__device__ __forceinline__ ull pack2(float v) {
    ull d; unsigned int u = __float_as_uint(v);
    asm("mov.b64 %0, {%1, %1};" : "=l"(d) : "r"(u));
    return d;
}
__device__ __forceinline__ float2 unpack2(ull u) {
    float2 f;
    f.x = __uint_as_float((unsigned int)u);
    f.y = __uint_as_float((unsigned int)(u >> 32));
    return f;
}

// ---------------- K1: xbar partials (float4, 16 lines in flight) --------------
__global__ void __launch_bounds__(192) k_colsum(const float* __restrict__ x) {
    int pq = threadIdx.x;                 // p-quad 0..191
    int js = blockIdx.x;                  // 4 j-splits of 128
    int b  = blockIdx.y;
    const float4* xp = (const float4*)(x + ((size_t)b * J_ + (size_t)js * 128) * P_) + pq;
    float4 a0 = make_float4(0.f, 0.f, 0.f, 0.f), a1 = a0, a2 = a0, a3 = a0;
    #pragma unroll 8
    for (int j = 0; j < 128; j += 4) {
        float4 v0 = xp[(size_t)(j + 0) * 192];
        float4 v1 = xp[(size_t)(j + 1) * 192];
        float4 v2 = xp[(size_t)(j + 2) * 192];
        float4 v3 = xp[(size_t)(j + 3) * 192];
        a0.x += v0.x; a0.y += v0.y; a0.z += v0.z; a0.w += v0.w;
        a1.x += v1.x; a1.y += v1.y; a1.z += v1.z; a1.w += v1.w;
        a2.x += v2.x; a2.y += v2.y; a2.z += v2.z; a2.w += v2.w;
        a3.x += v3.x; a3.y += v3.y; a3.z += v3.z; a3.w += v3.w;
    }
    float4 s;
    s.x = (a0.x + a1.x) + (a2.x + a3.x);
    s.y = (a0.y + a1.y) + (a2.y + a3.y);
    s.z = (a0.z + a1.z) + (a2.z + a3.z);
    s.w = (a0.w + a1.w) + (a2.w + a3.w);
    *(float4*)(g_xbar[js] + b * P_ + 4 * pq) = s;
}

// ---------------- K2: s = src @ W_i, squash -> g_o (and out at final) ---------
// MODE 0: src = sum of 4 xbar partials (uniform c => scale 1/16)
// MODE 1: src = sum of 8 y partials [b][i][p]
// grid (i=16, bg=16), block 256 = 8 warps: warp w -> (b = w&3, phalf = w>>2).
template <int MODE>
__global__ void __launch_bounds__(256) k_s(const float* __restrict__ W,
                                           float* __restrict__ out) {
    int i  = blockIdx.x;
    int b0 = blockIdx.y * 4;
    __shared__ float  ys[4][P_];
    __shared__ float2 ss[8][32];
    for (int idx = threadIdx.x; idx < 4 * (P_ / 4); idx += 256) {
        int bb = idx / (P_ / 4), pq = idx - bb * (P_ / 4);
        float4 s;
        if (MODE == 0) {
            size_t off = (size_t)(b0 + bb) * P_;
            float4 v0 = ((const float4*)(g_xbar[0] + off))[pq];
            float4 v1 = ((const float4*)(g_xbar[1] + off))[pq];
            float4 v2 = ((const float4*)(g_xbar[2] + off))[pq];
            float4 v3 = ((const float4*)(g_xbar[3] + off))[pq];
            s.x = (v0.x + v1.x) + (v2.x + v3.x);
            s.y = (v0.y + v1.y) + (v2.y + v3.y);
            s.z = (v0.z + v1.z) + (v2.z + v3.z);
            s.w = (v0.w + v1.w) + (v2.w + v3.w);
        } else {
            size_t off = ((size_t)(b0 + bb) * NC_ + i) * P_;
            s = make_float4(0.f, 0.f, 0.f, 0.f);
            #pragma unroll
            for (int sp = 0; sp < 8; sp++) {
                float4 v = ((const float4*)(g_yp[sp] + off))[pq];
                s.x += v.x; s.y += v.y; s.z += v.z; s.w += v.w;
            }
        }
        ((float4*)ys[bb])[pq] = s;
    }
    __syncthreads();

    int w = threadIdx.x >> 5, l = threadIdx.x & 31;
    int bb = w & 3, ph = w >> 2;
    const float* yrow = ys[bb] + ph * 384;
    const float* wrow = W + ((size_t)ph * 384) * WN_ + i * DC_ + 2 * l;

    float2 a[8];
    #pragma unroll
    for (int u = 0; u < 8; u++) a[u] = make_float2(0.f, 0.f);
    for (int p = 0; p < 384; p += 8) {
        #pragma unroll
        for (int u = 0; u < 8; u++) {
            float2 wv = *(const float2*)(wrow + (size_t)(p + u) * WN_);
            float yv = yrow[p + u];
            a[u].x += wv.x * yv; a[u].y += wv.y * yv;
        }
    }
    float2 acc;
    acc.x = ((a[0].x + a[1].x) + (a[2].x + a[3].x)) + ((a[4].x + a[5].x) + (a[6].x + a[7].x));
    acc.y = ((a[0].y + a[1].y) + (a[2].y + a[3].y)) + ((a[4].y + a[5].y) + (a[6].y + a[7].y));
    ss[w][l] = acc;
    __syncthreads();

    if (w < 4) {
        float2 p0 = ss[w][l], p1 = ss[w + 4][l];
        float2 s2 = make_float2(p0.x + p1.x, p0.y + p1.y);
        if (MODE == 0) { s2.x *= 0.0625f; s2.y *= 0.0625f; }
        float sq = s2.x * s2.x + s2.y * s2.y;
        #pragma unroll
        for (int s = 16; s > 0; s >>= 1) sq += __shfl_xor_sync(0xffffffffu, sq, s);
        float r = rsqrtf(sq + 1e-7f);
        s2.x *= r; s2.y *= r;
        size_t ob = ((size_t)(b0 + w) * NC_ + i) * DC_ + 2 * l;
        *(float2*)(g_o + ob) = s2;
        if (out) *(float2*)(out + ob) = s2;
    }
}

// ---------------- K3: vT[b][ip][p] = (W[p,2ip*64:].o, W[p,(2ip+1)*64:].o) -----
__global__ void __launch_bounds__(128) k_v(const float* __restrict__ W) {
    int pc = blockIdx.x * 16;
    int bg = blockIdx.y * 4;
    __shared__ float4 ws[16 * 256];   // 64KB, swizzled
    __shared__ float4 os[4][256];     // 16KB
    int t = threadIdx.x;

    for (int idx = t; idx < 4 * 256; idx += 128) {
        int bb = idx >> 8, q = idx & 255;
        os[bb][q] = ((const float4*)(g_o + (size_t)(bg + bb) * WN_))[q];
    }
    for (int idx = t; idx < 16 * 256; idx += 128) {
        int p = idx >> 8, q = idx & 255;
        float4 wv = ((const float4*)(W + (size_t)(pc + p) * WN_))[q];
        int qs = (q & ~15) | ((q & 15) ^ p);
        ws[p * 256 + qs] = wv;
    }
    __syncthreads();

    int p = t & 15, ip = t >> 4;
    float ax[4] = {0.f, 0.f, 0.f, 0.f};
    float ay[4] = {0.f, 0.f, 0.f, 0.f};
    #pragma unroll
    for (int qq = 0; qq < 32; qq++) {
        int q  = ip * 32 + qq;
        int qs = (q & ~15) | ((q & 15) ^ p);
        float4 wv = ws[p * 256 + qs];
        #pragma unroll
        for (int bb = 0; bb < 4; bb++) {
            float4 ov = os[bb][q];
            float d = wv.x * ov.x + wv.y * ov.y + wv.z * ov.z + wv.w * ov.w;
            if (qq < 16) ax[bb] += d; else ay[bb] += d;
        }
    }
    #pragma unroll
    for (int bb = 0; bb < 4; bb++)
        g_vT[bg + bb][ip][pc + p] = make_float2(ax[bb], ay[bb]);
}

// ---------------- K4: fused route (slab GEMM + softmax) + y partials ----------
// Register double-buffered slab staging: next slab's x/v prefetched into regs
// during current slab's compute, so staging is pure STS.
#define RY_XS   (128 * 68 * 4)     // 34816  xs[k][68]
#define RY_VT   (128 * 8 * 8)      //  8192  vt[k][8] float2
#define RY_PBL  (64 * 17 * 4)      //  4352
#define RY_CS   (64 * 4 * 16)      //  4096  cs[j][4] float4
#define RY_SMEM (RY_XS + RY_VT + RY_PBL + RY_CS)

__global__ void __launch_bounds__(256, 2) k_routey(const float* __restrict__ x) {
    extern __shared__ char sm[];
    float*  xs  = (float*)sm;
    float2* vt  = (float2*)(sm + RY_XS);
    float*  pbl = (float*)(sm + RY_XS + RY_VT);
    float4* cs  = (float4*)(sm + RY_XS + RY_VT + RY_PBL);

    int b  = blockIdx.y;
    int jc = blockIdx.x;
    const float* xb = x + ((size_t)b * J_ + jc * 64) * P_;
    int t = threadIdx.x, w = t >> 5, l = t & 31;
    int tj = l & 7, ti = l >> 3;

    for (int idx = t; idx < 64 * 17; idx += 256) pbl[idx] = 0.f;

    ull acc[16];
    #pragma unroll
    for (int q = 0; q < 16; q++) acc[q] = 0ull;

    const float2* vsrc = &g_vT[b][0][0];   // [ip][768]

    // per-thread staging coordinates
    int sj[8], skq[8];
    #pragma unroll
    for (int q = 0; q < 8; q++) {
        int m = q * 8 + w;
        sj[q]  = (m & 15) * 4 + (l & 3);
        skq[q] = (m >> 4) * 8 + (l >> 2);
    }

    // prologue: prefetch slab 0
    float4 rx[8];
    float2 rv[4];
    #pragma unroll
    for (int q = 0; q < 8; q++)
        rx[q] = ((const float4*)(xb + (size_t)sj[q] * P_))[skq[q]];
    #pragma unroll
    for (int q = 0; q < 4; q++) {
        int e = q * 256 + t;
        rv[q] = vsrc[(size_t)(e >> 7) * P_ + (e & 127)];
    }

    for (int s = 0; s < 6; s++) {
        __syncthreads();   // previous compute done reading xs/vt
        #pragma unroll
        for (int q = 0; q < 8; q++) {
            int kk = 4 * skq[q], j = sj[q];
            xs[(kk + 0) * 68 + j] = rx[q].x;
            xs[(kk + 1) * 68 + j] = rx[q].y;
            xs[(kk + 2) * 68 + j] = rx[q].z;
            xs[(kk + 3) * 68 + j] = rx[q].w;
        }
        #pragma unroll
        for (int q = 0; q < 4; q++) {
            int e = q * 256 + t;
            vt[(e & 127) * 8 + (e >> 7)] = rv[q];
        }
        __syncthreads();
        if (s < 5) {
            #pragma unroll
            for (int q = 0; q < 8; q++)
                rx[q] = ((const float4*)(xb + (size_t)sj[q] * P_ + 128 * (s + 1)))[skq[q]];
            #pragma unroll
            for (int q = 0; q < 4; q++) {
                int e = q * 256 + t;
                rv[q] = vsrc[(size_t)(e >> 7) * P_ + 128 * (s + 1) + (e & 127)];
            }
        }
        #pragma unroll
        for (int kk = 0; kk < 16; kk++) {
            int k = 16 * w + kk;
            float4 xa = *(const float4*)&xs[k * 68 + tj * 8];
            float4 xc = *(const float4*)&xs[k * 68 + tj * 8 + 4];
            ulonglong2 vv = *(const ulonglong2*)&vt[k * 8 + 2 * ti];
            acc[0]  = ffma2(pack2(xa.x), vv.x, acc[0]);
            acc[1]  = ffma2(pack2(xa.x), vv.y, acc[1]);
            acc[2]  = ffma2(pack2(xa.y), vv.x, acc[2]);
            acc[3]  = ffma2(pack2(xa.y), vv.y, acc[3]);
            acc[4]  = ffma2(pack2(xa.z), vv.x, acc[4]);
            acc[5]  = ffma2(pack2(xa.z), vv.y, acc[5]);
            acc[6]  = ffma2(pack2(xa.w), vv.x, acc[6]);
            acc[7]  = ffma2(pack2(xa.w), vv.y, acc[7]);
            acc[8]  = ffma2(pack2(xc.x), vv.x, acc[8]);
            acc[9]  = ffma2(pack2(xc.x), vv.y, acc[9]);
            acc[10] = ffma2(pack2(xc.y), vv.x, acc[10]);
            acc[11] = ffma2(pack2(xc.y), vv.y, acc[11]);
            acc[12] = ffma2(pack2(xc.z), vv.x, acc[12]);
            acc[13] = ffma2(pack2(xc.z), vv.y, acc[13]);
            acc[14] = ffma2(pack2(xc.w), vv.x, acc[14]);
            acc[15] = ffma2(pack2(xc.w), vv.y, acc[15]);
        }
    }
    __syncthreads();
    #pragma unroll
    for (int jj = 0; jj < 8; jj++) {
        int j = tj * 8 + jj;
        float2 f0 = unpack2(acc[jj * 2 + 0]);
        float2 f1 = unpack2(acc[jj * 2 + 1]);
        atomicAdd(&pbl[j * 17 + 4 * ti + 0], f0.x);
        atomicAdd(&pbl[j * 17 + 4 * ti + 1], f0.y);
        atomicAdd(&pbl[j * 17 + 4 * ti + 2], f1.x);
        atomicAdd(&pbl[j * 17 + 4 * ti + 3], f1.y);
    }
    __syncthreads();
    if (t < 64) {
        float bl[16];
        #pragma unroll
        for (int q = 0; q < 16; q++) bl[q] = pbl[t * 17 + q];
        float m = bl[0];
        #pragma unroll
        for (int q = 1; q < 16; q++) m = fmaxf(m, bl[q]);
        float sum = 0.f;
        #pragma unroll
        for (int q = 0; q < 16; q++) { bl[q] = __expf(bl[q] - m); sum += bl[q]; }
        float inv = 1.0f / sum;
        #pragma unroll
        for (int q = 0; q < 4; q++)
            cs[t * 4 + q] = make_float4(bl[4 * q] * inv, bl[4 * q + 1] * inv,
                                        bl[4 * q + 2] * inv, bl[4 * q + 3] * inv);
    }
    __syncthreads();

    ull ya[24];
    #pragma unroll
    for (int q = 0; q < 24; q++) ya[q] = 0ull;

    for (int j = 0; j < 64; j++) {
        float p0 = xb[(size_t)j * P_ + t];
        float p1 = xb[(size_t)j * P_ + t + 256];
        float p2 = xb[(size_t)j * P_ + t + 512];
        ull x0 = pack2(p0), x1 = pack2(p1), x2 = pack2(p2);
        const ulonglong2* crow = (const ulonglong2*)(cs + j * 4);
        ulonglong2 ca = crow[0];
        ya[0]  = ffma2(x0, ca.x, ya[0]);  ya[8]  = ffma2(x1, ca.x, ya[8]);  ya[16] = ffma2(x2, ca.x, ya[16]);
        ya[1]  = ffma2(x0, ca.y, ya[1]);  ya[9]  = ffma2(x1, ca.y, ya[9]);  ya[17] = ffma2(x2, ca.y, ya[17]);
        ulonglong2 cb2 = crow[1];
        ya[2]  = ffma2(x0, cb2.x, ya[2]); ya[10] = ffma2(x1, cb2.x, ya[10]); ya[18] = ffma2(x2, cb2.x, ya[18]);
        ya[3]  = ffma2(x0, cb2.y, ya[3]); ya[11] = ffma2(x1, cb2.y, ya[11]); ya[19] = ffma2(x2, cb2.y, ya[19]);
        ulonglong2 cc = crow[2];
        ya[4]  = ffma2(x0, cc.x, ya[4]);  ya[12] = ffma2(x1, cc.x, ya[12]); ya[20] = ffma2(x2, cc.x, ya[20]);
        ya[5]  = ffma2(x0, cc.y, ya[5]);  ya[13] = ffma2(x1, cc.y, ya[13]); ya[21] = ffma2(x2, cc.y, ya[21]);
        ulonglong2 cd = crow[3];
        ya[6]  = ffma2(x0, cd.x, ya[6]);  ya[14] = ffma2(x1, cd.x, ya[14]); ya[22] = ffma2(x2, cd.x, ya[22]);
        ya[7]  = ffma2(x0, cd.y, ya[7]);  ya[15] = ffma2(x1, cd.y, ya[15]); ya[23] = ffma2(x2, cd.y, ya[23]);
    }
    #pragma unroll
    for (int pp = 0; pp < 3; pp++) {
        #pragma unroll
        for (int q = 0; q < 8; q++) {
            float2 f = unpack2(ya[pp * 8 + q]);
            g_yp[jc][((size_t)b * NC_ + 2 * q)     * P_ + pp * 256 + t] = f.x;
            g_yp[jc][((size_t)b * NC_ + 2 * q + 1) * P_ + pp * 256 + t] = f.y;
        }
    }
}

// ---------------- launch ----------------
extern "C" void kernel_launch(void* const* d_in, const int* in_sizes, int n_in,
                              void* d_out, int out_size) {
    const float* x = (const float*)d_in[0];
    const float* W = (const float*)d_in[1];
    if (n_in >= 2 && in_sizes[0] < in_sizes[1]) {
        const float* tmp = x; x = W; W = tmp;
    }
    float* out = (float*)d_out;
    (void)out_size;

    cudaFuncSetAttribute(k_routey, cudaFuncAttributeMaxDynamicSharedMemorySize,
                         RY_SMEM);

    dim3 gsq(16, 16);

    k_colsum<<<dim3(4, 64), 192>>>(x);
    k_s<0><<<gsq, 256>>>(W, nullptr);
    k_v<<<dim3(48, 16), 128>>>(W);

    // iteration 1
    k_routey<<<dim3(8, 64), 256, RY_SMEM>>>(x);
    k_s<1><<<gsq, 256>>>(W, nullptr);
    k_v<<<dim3(48, 16), 128>>>(W);

    // iteration 2 (final)
    k_routey<<<dim3(8, 64), 256, RY_SMEM>>>(x);
    k_s<1><<<gsq, 256>>>(W, out);
}

// round 7
// speedup vs baseline: 1.7983x; 1.2226x over previous
#include <cuda_runtime.h>

#define B_  64
#define J_  512
#define P_  768
#define NC_ 16
#define DC_ 64
#define WN_ 1024   // NC_*DC_

typedef unsigned long long ull;

// ---------------- scratch (device globals; no allocation allowed) ----------------
__device__ float  g_xbar[4][B_ * P_];       // colsum partials [jsplit][b*P+p]
__device__ float  g_o[B_ * WN_];            // routed outputs  [b][i*64+k]
__device__ float2 g_v2[B_][P_][18];         // v duplicated    [b][p][i]=(v,v), pitch 18
__device__ float  g_yp[8][B_ * NC_ * P_];   // y partials      [jsplit][b][i][p]

// ---------------- packed f32x2 helpers ----------------
__device__ __forceinline__ ull ffma2(ull a, ull b, ull c) {
    ull d;
    asm("fma.rn.f32x2 %0, %1, %2, %3;" : "=l"(d) : "l"(a), "l"(b), "l"(c));
    return d;
}
__device__ __forceinline__ ull pack2(float v) {
    ull d; unsigned int u = __float_as_uint(v);
    asm("mov.b64 %0, {%1, %1};" : "=l"(d) : "r"(u));
    return d;
}
__device__ __forceinline__ float2 unpack2(ull u) {
    float2 f;
    f.x = __uint_as_float((unsigned int)u);
    f.y = __uint_as_float((unsigned int)(u >> 32));
    return f;
}

// ---------------- K1: xbar partials (float4, 16 lines in flight) --------------
__global__ void __launch_bounds__(192) k_colsum(const float* __restrict__ x) {
    int pq = threadIdx.x;
    int js = blockIdx.x;
    int b  = blockIdx.y;
    const float4* xp = (const float4*)(x + ((size_t)b * J_ + (size_t)js * 128) * P_) + pq;
    float4 a0 = make_float4(0.f, 0.f, 0.f, 0.f), a1 = a0, a2 = a0, a3 = a0;
    #pragma unroll 8
    for (int j = 0; j < 128; j += 4) {
        float4 v0 = xp[(size_t)(j + 0) * 192];
        float4 v1 = xp[(size_t)(j + 1) * 192];
        float4 v2 = xp[(size_t)(j + 2) * 192];
        float4 v3 = xp[(size_t)(j + 3) * 192];
        a0.x += v0.x; a0.y += v0.y; a0.z += v0.z; a0.w += v0.w;
        a1.x += v1.x; a1.y += v1.y; a1.z += v1.z; a1.w += v1.w;
        a2.x += v2.x; a2.y += v2.y; a2.z += v2.z; a2.w += v2.w;
        a3.x += v3.x; a3.y += v3.y; a3.z += v3.z; a3.w += v3.w;
    }
    float4 s;
    s.x = (a0.x + a1.x) + (a2.x + a3.x);
    s.y = (a0.y + a1.y) + (a2.y + a3.y);
    s.z = (a0.z + a1.z) + (a2.z + a3.z);
    s.w = (a0.w + a1.w) + (a2.w + a3.w);
    *(float4*)(g_xbar[js] + b * P_ + 4 * pq) = s;
}

// ---------------- K2: s = src @ W_i, squash -> g_o (and out at final) ---------
// grid (i=16, bg=16), block 512 = 16 warps: warp -> (b = w&3, pquarter = w>>2).
template <int MODE>
__global__ void __launch_bounds__(512) k_s(const float* __restrict__ W,
                                           float* __restrict__ out) {
    int i  = blockIdx.x;
    int b0 = blockIdx.y * 4;
    __shared__ float  ys[4][P_];
    __shared__ float2 ss[4][4][32];
    for (int idx = threadIdx.x; idx < 4 * (P_ / 4); idx += 512) {
        int bb = idx / (P_ / 4), pq = idx - bb * (P_ / 4);
        float4 s;
        if (MODE == 0) {
            size_t off = (size_t)(b0 + bb) * P_;
            float4 v0 = ((const float4*)(g_xbar[0] + off))[pq];
            float4 v1 = ((const float4*)(g_xbar[1] + off))[pq];
            float4 v2 = ((const float4*)(g_xbar[2] + off))[pq];
            float4 v3 = ((const float4*)(g_xbar[3] + off))[pq];
            s.x = (v0.x + v1.x) + (v2.x + v3.x);
            s.y = (v0.y + v1.y) + (v2.y + v3.y);
            s.z = (v0.z + v1.z) + (v2.z + v3.z);
            s.w = (v0.w + v1.w) + (v2.w + v3.w);
        } else {
            size_t off = ((size_t)(b0 + bb) * NC_ + i) * P_;
            s = make_float4(0.f, 0.f, 0.f, 0.f);
            #pragma unroll
            for (int sp = 0; sp < 8; sp++) {
                float4 v = ((const float4*)(g_yp[sp] + off))[pq];
                s.x += v.x; s.y += v.y; s.z += v.z; s.w += v.w;
            }
        }
        ((float4*)ys[bb])[pq] = s;
    }
    __syncthreads();

    int w = threadIdx.x >> 5, l = threadIdx.x & 31;
    int bb = w & 3, ph = w >> 2;                 // p-quarter 0..3
    const float* yrow = ys[bb] + ph * 192;
    const float* wrow = W + ((size_t)ph * 192) * WN_ + i * DC_ + 2 * l;

    float2 a[8];
    #pragma unroll
    for (int u = 0; u < 8; u++) a[u] = make_float2(0.f, 0.f);
    for (int p = 0; p < 192; p += 8) {
        #pragma unroll
        for (int u = 0; u < 8; u++) {
            float2 wv = *(const float2*)(wrow + (size_t)(p + u) * WN_);
            float yv = yrow[p + u];
            a[u].x += wv.x * yv; a[u].y += wv.y * yv;
        }
    }
    float2 acc;
    acc.x = ((a[0].x + a[1].x) + (a[2].x + a[3].x)) + ((a[4].x + a[5].x) + (a[6].x + a[7].x));
    acc.y = ((a[0].y + a[1].y) + (a[2].y + a[3].y)) + ((a[4].y + a[5].y) + (a[6].y + a[7].y));
    ss[ph][bb][l] = acc;
    __syncthreads();

    if (w < 4) {
        float2 p0 = ss[0][w][l], p1 = ss[1][w][l], p2 = ss[2][w][l], p3 = ss[3][w][l];
        float2 s2 = make_float2((p0.x + p1.x) + (p2.x + p3.x),
                                (p0.y + p1.y) + (p2.y + p3.y));
        if (MODE == 0) { s2.x *= 0.0625f; s2.y *= 0.0625f; }
        float sq = s2.x * s2.x + s2.y * s2.y;
        #pragma unroll
        for (int s = 16; s > 0; s >>= 1) sq += __shfl_xor_sync(0xffffffffu, sq, s);
        float r = rsqrtf(sq + 1e-7f);
        s2.x *= r; s2.y *= r;
        size_t ob = ((size_t)(b0 + w) * NC_ + i) * DC_ + 2 * l;
        *(float2*)(g_o + ob) = s2;
        if (out) *(float2*)(out + ob) = s2;
    }
}

// ---------------- K3: v2[b][p][i] = (W[p,i*64:].o[b,i,:]) duplicated ----------
__global__ void __launch_bounds__(128) k_v(const float* __restrict__ W) {
    int pc = blockIdx.x * 16;
    int bg = blockIdx.y * 4;
    __shared__ float4 ws[16 * 256];   // 64KB, swizzled
    __shared__ float4 os[4][256];     // 16KB
    int t = threadIdx.x;

    for (int idx = t; idx < 4 * 256; idx += 128) {
        int bb = idx >> 8, q = idx & 255;
        os[bb][q] = ((const float4*)(g_o + (size_t)(bg + bb) * WN_))[q];
    }
    for (int idx = t; idx < 16 * 256; idx += 128) {
        int p = idx >> 8, q = idx & 255;
        float4 wv = ((const float4*)(W + (size_t)(pc + p) * WN_))[q];
        int qs = (q & ~15) | ((q & 15) ^ p);
        ws[p * 256 + qs] = wv;
    }
    __syncthreads();

    int p = t & 15, ip = t >> 4;     // ip in 0..7 (i-pair)
    float ax[4] = {0.f, 0.f, 0.f, 0.f};
    float ay[4] = {0.f, 0.f, 0.f, 0.f};
    #pragma unroll
    for (int qq = 0; qq < 32; qq++) {
        int q  = ip * 32 + qq;
        int qs = (q & ~15) | ((q & 15) ^ p);
        float4 wv = ws[p * 256 + qs];
        #pragma unroll
        for (int bb = 0; bb < 4; bb++) {
            float4 ov = os[bb][q];
            float d = wv.x * ov.x + wv.y * ov.y + wv.z * ov.z + wv.w * ov.w;
            if (qq < 16) ax[bb] += d; else ay[bb] += d;
        }
    }
    #pragma unroll
    for (int bb = 0; bb < 4; bb++) {
        g_v2[bg + bb][pc + p][2 * ip]     = make_float2(ax[bb], ax[bb]);
        g_v2[bg + bb][pc + p][2 * ip + 1] = make_float2(ay[bb], ay[bb]);
    }
}

// ---------------- K4: fused route (slab GEMM + softmax) + y partials ----------
// xs: swizzled transposed x tile, unit(16B) = k*16 + (jq ^ ((k>>2)&15)), 32KB.
// vt2: duplicated v slab copy, float2 pitch 18 per k, 18KB.
// Thread tile: 8j x 4i. Inner loop: 16 FFMA2 + 4 LDS.128, zero MOVs.
#define RY_XS   (128 * 16 * 16)    // 32768
#define RY_VT   (128 * 18 * 8)     // 18432  (1152 x 16B)
#define RY_PBL  (64 * 17 * 4)      //  4352
#define RY_CS   (64 * 4 * 16)      //  4096
#define RY_SMEM (RY_XS + RY_VT + RY_PBL + RY_CS)

__global__ void __launch_bounds__(256, 2) k_routey(const float* __restrict__ x) {
    extern __shared__ char sm[];
    float*      xsf  = (float*)sm;                    // scalar view of xs units
    ulonglong2* xs16 = (ulonglong2*)sm;               // 16B-unit view
    float2*     vt2  = (float2*)(sm + RY_XS);         // [k][18]
    uint4*      vt2u = (uint4*)(sm + RY_XS);
    float*      pbl  = (float*)(sm + RY_XS + RY_VT);
    float4*     cs   = (float4*)(sm + RY_XS + RY_VT + RY_PBL);

    int b  = blockIdx.y;
    int jc = blockIdx.x;
    const float* xb = x + ((size_t)b * J_ + jc * 64) * P_;
    int t = threadIdx.x, w = t >> 5, l = t & 31;
    int tj = l & 7, ti = l >> 3;                      // 8j-octet, 4i-quad

    for (int idx = t; idx < 64 * 17; idx += 256) pbl[idx] = 0.f;

    ull acc[16];
    #pragma unroll
    for (int q = 0; q < 16; q++) acc[q] = 0ull;

    const uint4* v2src = (const uint4*)&g_v2[b][0][0];   // 9 units per p-row

    // staging coordinates
    int sj[8], skq[8];
    #pragma unroll
    for (int q = 0; q < 8; q++) {
        int m = q * 8 + w;
        sj[q]  = (m & 15) * 4 + (l & 3);
        skq[q] = (m >> 4) * 8 + (l >> 2);   // 0..31 (float4-k unit)
    }

    // prologue: prefetch slab 0
    float4 rx[8];
    uint4  rv[5];
    #pragma unroll
    for (int q = 0; q < 8; q++)
        rx[q] = ((const float4*)(xb + (size_t)sj[q] * P_))[skq[q]];
    #pragma unroll
    for (int q = 0; q < 5; q++) {
        int idx = t + 256 * q;
        if (idx < 1152) rv[q] = v2src[idx];
    }

    for (int s = 0; s < 6; s++) {
        __syncthreads();
        // xs transpose store (conflict-free via xor swizzle)
        #pragma unroll
        for (int q = 0; q < 8; q++) {
            int jq = sj[q] >> 2, jr = sj[q] & 3;
            int swz = jq ^ (skq[q] & 15);
            int base = (4 * skq[q]) * 16 + swz;
            xsf[(base + 0 * 16) * 4 + jr] = rx[q].x;
            xsf[(base + 1 * 16) * 4 + jr] = rx[q].y;
            xsf[(base + 2 * 16) * 4 + jr] = rx[q].z;
            xsf[(base + 3 * 16) * 4 + jr] = rx[q].w;
        }
        // vt2 straight copy
        #pragma unroll
        for (int q = 0; q < 5; q++) {
            int idx = t + 256 * q;
            if (idx < 1152) vt2u[idx] = rv[q];
        }
        __syncthreads();
        if (s < 5) {
            #pragma unroll
            for (int q = 0; q < 8; q++)
                rx[q] = ((const float4*)(xb + (size_t)sj[q] * P_ + 128 * (s + 1)))[skq[q]];
            #pragma unroll
            for (int q = 0; q < 5; q++) {
                int idx = t + 256 * q;
                if (idx < 1152) rv[q] = v2src[(size_t)(s + 1) * 1152 + idx];
            }
        }
        // compute: warp's k sub-range [16w, 16w+16)
        #pragma unroll
        for (int kk = 0; kk < 16; kk++) {
            int k = 16 * w + kk;
            int sw = (k >> 2) & 15;
            ulonglong2 xp0 = xs16[k * 16 + ((2 * tj)     ^ sw)];
            ulonglong2 xp1 = xs16[k * 16 + ((2 * tj + 1) ^ sw)];
            ulonglong2 v01 = *(const ulonglong2*)&vt2[k * 18 + 4 * ti];
            ulonglong2 v23 = *(const ulonglong2*)&vt2[k * 18 + 4 * ti + 2];
            acc[0]  = ffma2(xp0.x, v01.x, acc[0]);
            acc[1]  = ffma2(xp0.x, v01.y, acc[1]);
            acc[2]  = ffma2(xp0.x, v23.x, acc[2]);
            acc[3]  = ffma2(xp0.x, v23.y, acc[3]);
            acc[4]  = ffma2(xp0.y, v01.x, acc[4]);
            acc[5]  = ffma2(xp0.y, v01.y, acc[5]);
            acc[6]  = ffma2(xp0.y, v23.x, acc[6]);
            acc[7]  = ffma2(xp0.y, v23.y, acc[7]);
            acc[8]  = ffma2(xp1.x, v01.x, acc[8]);
            acc[9]  = ffma2(xp1.x, v01.y, acc[9]);
            acc[10] = ffma2(xp1.x, v23.x, acc[10]);
            acc[11] = ffma2(xp1.x, v23.y, acc[11]);
            acc[12] = ffma2(xp1.y, v01.x, acc[12]);
            acc[13] = ffma2(xp1.y, v01.y, acc[13]);
            acc[14] = ffma2(xp1.y, v23.x, acc[14]);
            acc[15] = ffma2(xp1.y, v23.y, acc[15]);
        }
    }
    __syncthreads();
    // merge k-slice partial logits: thread owns j = 8tj+2jp(+1), i = 4ti+ii
    #pragma unroll
    for (int jp = 0; jp < 4; jp++) {
        int j0 = 8 * tj + 2 * jp;
        #pragma unroll
        for (int ii = 0; ii < 4; ii++) {
            float2 f = unpack2(acc[4 * jp + ii]);
            atomicAdd(&pbl[j0 * 17 + 4 * ti + ii], f.x);
            atomicAdd(&pbl[(j0 + 1) * 17 + 4 * ti + ii], f.y);
        }
    }
    __syncthreads();
    if (t < 64) {
        float bl[16];
        #pragma unroll
        for (int q = 0; q < 16; q++) bl[q] = pbl[t * 17 + q];
        float m = bl[0];
        #pragma unroll
        for (int q = 1; q < 16; q++) m = fmaxf(m, bl[q]);
        float sum = 0.f;
        #pragma unroll
        for (int q = 0; q < 16; q++) { bl[q] = __expf(bl[q] - m); sum += bl[q]; }
        float inv = 1.0f / sum;
        #pragma unroll
        for (int q = 0; q < 4; q++)
            cs[t * 4 + q] = make_float4(bl[4 * q] * inv, bl[4 * q + 1] * inv,
                                        bl[4 * q + 2] * inv, bl[4 * q + 3] * inv);
    }
    __syncthreads();

    // ---- y phase: thread owns p in {t, t+256, t+512}, all 16 i ----
    ull ya[24];
    #pragma unroll
    for (int q = 0; q < 24; q++) ya[q] = 0ull;

    for (int j = 0; j < 64; j++) {
        float p0 = xb[(size_t)j * P_ + t];
        float p1 = xb[(size_t)j * P_ + t + 256];
        float p2 = xb[(size_t)j * P_ + t + 512];
        ull x0 = pack2(p0), x1 = pack2(p1), x2 = pack2(p2);
        const ulonglong2* crow = (const ulonglong2*)(cs + j * 4);
        ulonglong2 ca = crow[0];
        ya[0]  = ffma2(x0, ca.x, ya[0]);  ya[8]  = ffma2(x1, ca.x, ya[8]);  ya[16] = ffma2(x2, ca.x, ya[16]);
        ya[1]  = ffma2(x0, ca.y, ya[1]);  ya[9]  = ffma2(x1, ca.y, ya[9]);  ya[17] = ffma2(x2, ca.y, ya[17]);
        ulonglong2 cb2 = crow[1];
        ya[2]  = ffma2(x0, cb2.x, ya[2]); ya[10] = ffma2(x1, cb2.x, ya[10]); ya[18] = ffma2(x2, cb2.x, ya[18]);
        ya[3]  = ffma2(x0, cb2.y, ya[3]); ya[11] = ffma2(x1, cb2.y, ya[11]); ya[19] = ffma2(x2, cb2.y, ya[19]);
        ulonglong2 cc = crow[2];
        ya[4]  = ffma2(x0, cc.x, ya[4]);  ya[12] = ffma2(x1, cc.x, ya[12]); ya[20] = ffma2(x2, cc.x, ya[20]);
        ya[5]  = ffma2(x0, cc.y, ya[5]);  ya[13] = ffma2(x1, cc.y, ya[13]); ya[21] = ffma2(x2, cc.y, ya[21]);
        ulonglong2 cd = crow[3];
        ya[6]  = ffma2(x0, cd.x, ya[6]);  ya[14] = ffma2(x1, cd.x, ya[14]); ya[22] = ffma2(x2, cd.x, ya[22]);
        ya[7]  = ffma2(x0, cd.y, ya[7]);  ya[15] = ffma2(x1, cd.y, ya[15]); ya[23] = ffma2(x2, cd.y, ya[23]);
    }
    #pragma unroll
    for (int pp = 0; pp < 3; pp++) {
        #pragma unroll
        for (int q = 0; q < 8; q++) {
            float2 f = unpack2(ya[pp * 8 + q]);
            g_yp[jc][((size_t)b * NC_ + 2 * q)     * P_ + pp * 256 + t] = f.x;
            g_yp[jc][((size_t)b * NC_ + 2 * q + 1) * P_ + pp * 256 + t] = f.y;
        }
    }
}

// ---------------- launch ----------------
extern "C" void kernel_launch(void* const* d_in, const int* in_sizes, int n_in,
                              void* d_out, int out_size) {
    const float* x = (const float*)d_in[0];
    const float* W = (const float*)d_in[1];
    if (n_in >= 2 && in_sizes[0] < in_sizes[1]) {
        const float* tmp = x; x = W; W = tmp;
    }
    float* out = (float*)d_out;
    (void)out_size;

    cudaFuncSetAttribute(k_routey, cudaFuncAttributeMaxDynamicSharedMemorySize,
                         RY_SMEM);

    dim3 gsq(16, 16);

    k_colsum<<<dim3(4, 64), 192>>>(x);
    k_s<0><<<gsq, 512>>>(W, nullptr);
    k_v<<<dim3(48, 16), 128>>>(W);

    // iteration 1
    k_routey<<<dim3(8, 64), 256, RY_SMEM>>>(x);
    k_s<1><<<gsq, 512>>>(W, nullptr);
    k_v<<<dim3(48, 16), 128>>>(W);

    // iteration 2 (final)
    k_routey<<<dim3(8, 64), 256, RY_SMEM>>>(x);
    k_s<1><<<gsq, 512>>>(W, out);
}